// round 1
// baseline (speedup 1.0000x reference)
#include <cuda_runtime.h>
#include <cuda_bf16.h>
#include <math.h>

// ---------------------------------------------------------------------------
// PEER-LoRA fused pipeline.
//
// Shapes (fixed for this problem):
//   B=4, N=2048 -> T=8192 tokens, DIM=1024, HEADS=8, NUM_KEYS=128,
//   DIM_KEY=512, DIM_INNER=2048, NUM_EXPERTS=16384, TOPK=1 (per head).
//
// Algebraic simplifications vs the reference:
//   * top-1 of (top16 x + top16 y) == argmax(sim0) (+) argmax(sim1).
//   * sim = (x @ Wq^T) . keys  ==  x @ M^T  with M = fold(keys, Wq).
// ---------------------------------------------------------------------------

#define T_TOK   8192
#define DIM     1024
#define DINNER  2048
#define HEADS   8
#define NKEYS   128
#define DKEY    512

// Scratch (device globals; no runtime allocation allowed)
__device__ float g_M[2048 * 1024];        // folded key matrix [ (p,h,k), d ]
__device__ float g_sim[T_TOK * 2048];     // sim [t][p*1024 + h*128 + k]
__device__ float g_hid[T_TOK * DINNER];   // hidden (pre-act, then post-act)
__device__ int   g_idx[T_TOK * HEADS];
__device__ float g_gate[T_TOK * HEADS];

// ---------------------------------------------------------------------------
// Generic tiled fp32 GEMM:  C[i,j] = sum_k A[i,k] * B[j,k]
//   A: [M,K] row-major (lda).   B: normal -> [N,K] row-major (ldb);
//   TRANSB -> B element (j,k) read at B[k*ldb + j].
//   Batched over blockIdx.z with decomposed offsets:
//     z -> zh = z / zdiv, zl = z % zdiv; off = zh*s_hi + zl*s_lo.
// ---------------------------------------------------------------------------
#define BM 128
#define BN 128
#define BK 16
#define BMP 132   // padded row: 132 floats = 528 B = 33*16 B (16B aligned rows)

template <bool TRANSB>
__global__ __launch_bounds__(256) void gemm_tn(
    const float* __restrict__ Ab, const float* __restrict__ Bb,
    float* __restrict__ Cb,
    int M, int N, int K, int lda, int ldb, int ldc,
    int zdiv,
    size_t sah, size_t sal, size_t sbh, size_t sbl, size_t sch, size_t scl)
{
    int z = blockIdx.z;
    int zh = z / zdiv, zl = z % zdiv;
    const float* A = Ab + zh * sah + zl * sal;
    const float* B = Bb + zh * sbh + zl * sbl;
    float*       C = Cb + zh * sch + zl * scl;

    const int m0 = blockIdx.y * BM;
    const int n0 = blockIdx.x * BN;
    const int tid = threadIdx.x;

    __shared__ __align__(16) float As[2][BK][BMP];
    __shared__ __align__(16) float Bs[2][BK][BMP];

    // A-load mapping (also non-trans B): 2 float4 per thread along k
    const int rowA = tid >> 2;          // 0..63 (+64 for second load)
    const int kkA  = (tid & 3) * 4;
    const float* Ab0 = A + (size_t)(m0 + rowA) * lda + kkA;
    const float* Ab1 = Ab0 + (size_t)64 * lda;

    // B pointers
    const float *Bb0, *Bb1;
    int kkB = 0, jfB = 0;
    if (TRANSB) {
        kkB = tid >> 4;                 // 0..15
        jfB = tid & 15;                 // float4 slot
        Bb0 = B + (size_t)kkB * ldb + n0 + jfB * 4;
        Bb1 = Bb0 + 64;
    } else {
        Bb0 = B + (size_t)(n0 + rowA) * ldb + kkA;
        Bb1 = Bb0 + (size_t)64 * ldb;
    }

    const int tm = (tid >> 4) * 8;
    const int tn = (tid & 15) * 8;

    float acc[8][8];
#pragma unroll
    for (int i = 0; i < 8; i++)
#pragma unroll
        for (int j = 0; j < 8; j++) acc[i][j] = 0.f;

    const int nk = K / BK;

    // ---- prologue: tile 0 straight into smem buffer 0
    {
        float4 ra0 = *(const float4*)(Ab0);
        float4 ra1 = *(const float4*)(Ab1);
        As[0][kkA + 0][rowA]      = ra0.x; As[0][kkA + 1][rowA]      = ra0.y;
        As[0][kkA + 2][rowA]      = ra0.z; As[0][kkA + 3][rowA]      = ra0.w;
        As[0][kkA + 0][rowA + 64] = ra1.x; As[0][kkA + 1][rowA + 64] = ra1.y;
        As[0][kkA + 2][rowA + 64] = ra1.z; As[0][kkA + 3][rowA + 64] = ra1.w;
        float4 rb0 = *(const float4*)(Bb0);
        float4 rb1 = *(const float4*)(Bb1);
        if (TRANSB) {
            *(float4*)&Bs[0][kkB][jfB * 4]      = rb0;
            *(float4*)&Bs[0][kkB][jfB * 4 + 64] = rb1;
        } else {
            Bs[0][kkA + 0][rowA]      = rb0.x; Bs[0][kkA + 1][rowA]      = rb0.y;
            Bs[0][kkA + 2][rowA]      = rb0.z; Bs[0][kkA + 3][rowA]      = rb0.w;
            Bs[0][kkA + 0][rowA + 64] = rb1.x; Bs[0][kkA + 1][rowA + 64] = rb1.y;
            Bs[0][kkA + 2][rowA + 64] = rb1.z; Bs[0][kkA + 3][rowA + 64] = rb1.w;
        }
    }
    __syncthreads();

    for (int kt = 0; kt < nk; kt++) {
        const int cur = kt & 1;
        const int nxt = cur ^ 1;

        float4 ra0, ra1, rb0, rb1;
        const bool more = (kt + 1 < nk);
        if (more) {
            const int kk = (kt + 1) * BK;
            ra0 = *(const float4*)(Ab0 + kk);
            ra1 = *(const float4*)(Ab1 + kk);
            if (TRANSB) {
                rb0 = *(const float4*)(Bb0 + (size_t)kk * ldb);
                rb1 = *(const float4*)(Bb1 + (size_t)kk * ldb);
            } else {
                rb0 = *(const float4*)(Bb0 + kk);
                rb1 = *(const float4*)(Bb1 + kk);
            }
        }

#pragma unroll
        for (int k = 0; k < BK; k++) {
            float4 a0 = *(const float4*)&As[cur][k][tm];
            float4 a1 = *(const float4*)&As[cur][k][tm + 4];
            float4 b0 = *(const float4*)&Bs[cur][k][tn];
            float4 b1 = *(const float4*)&Bs[cur][k][tn + 4];
            float av[8] = {a0.x, a0.y, a0.z, a0.w, a1.x, a1.y, a1.z, a1.w};
            float bv[8] = {b0.x, b0.y, b0.z, b0.w, b1.x, b1.y, b1.z, b1.w};
#pragma unroll
            for (int i = 0; i < 8; i++)
#pragma unroll
                for (int j = 0; j < 8; j++)
                    acc[i][j] = fmaf(av[i], bv[j], acc[i][j]);
        }

        if (more) {
            As[nxt][kkA + 0][rowA]      = ra0.x; As[nxt][kkA + 1][rowA]      = ra0.y;
            As[nxt][kkA + 2][rowA]      = ra0.z; As[nxt][kkA + 3][rowA]      = ra0.w;
            As[nxt][kkA + 0][rowA + 64] = ra1.x; As[nxt][kkA + 1][rowA + 64] = ra1.y;
            As[nxt][kkA + 2][rowA + 64] = ra1.z; As[nxt][kkA + 3][rowA + 64] = ra1.w;
            if (TRANSB) {
                *(float4*)&Bs[nxt][kkB][jfB * 4]      = rb0;
                *(float4*)&Bs[nxt][kkB][jfB * 4 + 64] = rb1;
            } else {
                Bs[nxt][kkA + 0][rowA]      = rb0.x; Bs[nxt][kkA + 1][rowA]      = rb0.y;
                Bs[nxt][kkA + 2][rowA]      = rb0.z; Bs[nxt][kkA + 3][rowA]      = rb0.w;
                Bs[nxt][kkA + 0][rowA + 64] = rb1.x; Bs[nxt][kkA + 1][rowA + 64] = rb1.y;
                Bs[nxt][kkA + 2][rowA + 64] = rb1.z; Bs[nxt][kkA + 3][rowA + 64] = rb1.w;
            }
        }
        __syncthreads();
    }

#pragma unroll
    for (int i = 0; i < 8; i++) {
        float* cp = C + (size_t)(m0 + tm + i) * ldc + n0 + tn;
        float4 v0 = {acc[i][0], acc[i][1], acc[i][2], acc[i][3]};
        float4 v1 = {acc[i][4], acc[i][5], acc[i][6], acc[i][7]};
        *(float4*)cp       = v0;
        *(float4*)(cp + 4) = v1;
    }
}

// ---------------------------------------------------------------------------
// Select: per (t,h): argmax over 128 for p=0 and p=1 ->
//   idx = arg0*128 + arg1, gate = relu(max0 + max1).
// One warp per (t,h).
// ---------------------------------------------------------------------------
__global__ __launch_bounds__(256) void select_kernel(
    const float* __restrict__ sim, int* __restrict__ idx_out,
    float* __restrict__ gate_out)
{
    const int gw = (blockIdx.x * blockDim.x + threadIdx.x) >> 5;
    const int lane = threadIdx.x & 31;
    if (gw >= T_TOK * HEADS) return;
    const int t = gw >> 3;
    const int h = gw & 7;

    float bv[2];
    int bi[2];
#pragma unroll
    for (int p = 0; p < 2; p++) {
        const float* s = sim + (size_t)t * 2048 + p * 1024 + h * 128;
        float best = -1e30f;
        int bk = 0;
#pragma unroll
        for (int u = 0; u < 4; u++) {
            int k = lane + u * 32;
            float v = s[k];
            if (v > best) { best = v; bk = k; }
        }
#pragma unroll
        for (int o = 16; o; o >>= 1) {
            float ov = __shfl_down_sync(0xffffffffu, best, o);
            int   ok = __shfl_down_sync(0xffffffffu, bk, o);
            if (ov > best || (ov == best && ok < bk)) { best = ov; bk = ok; }
        }
        bv[p] = best;
        bi[p] = bk;
    }
    if (lane == 0) {
        float sc = bv[0] + bv[1];
        gate_out[gw] = sc > 0.f ? sc : 0.f;
        idx_out[gw] = bi[0] * NKEYS + bi[1];
    }
}

// ---------------------------------------------------------------------------
// Fuse 1: hidden[t] = gelu( hidden_pre[t] + sum_h gate*(x[t].in_a[i_h])*in_b[i_h] )
// One block (256 thr) per token; 8 concurrent expert-row streams.
// ---------------------------------------------------------------------------
__global__ __launch_bounds__(256) void fuse_in_kernel(
    const float* __restrict__ x, const float* __restrict__ in_a,
    const float* __restrict__ in_b, const int* __restrict__ idx,
    const float* __restrict__ gate, float* __restrict__ hidden)
{
    const int t = blockIdx.x;
    const int tid = threadIdx.x;
    __shared__ __align__(16) float xs[DIM];
    __shared__ float red[8][HEADS];
    __shared__ float lin_s[HEADS];

    const float* xp = x + (size_t)t * DIM;
    for (int i = tid; i < DIM; i += 256) xs[i] = xp[i];

    int id[HEADS];
    float gt[HEADS];
#pragma unroll
    for (int h = 0; h < HEADS; h++) {
        id[h] = idx[t * HEADS + h];
        gt[h] = gate[t * HEADS + h];
    }
    __syncthreads();

    float part[HEADS];
#pragma unroll
    for (int h = 0; h < HEADS; h++) part[h] = 0.f;
#pragma unroll
    for (int i = 0; i < DIM / 256; i++) {
        const int d = tid + i * 256;
        const float xv = xs[d];
#pragma unroll
        for (int h = 0; h < HEADS; h++)
            part[h] = fmaf(xv, __ldg(&in_a[(size_t)id[h] * DIM + d]), part[h]);
    }
#pragma unroll
    for (int h = 0; h < HEADS; h++)
#pragma unroll
        for (int o = 16; o; o >>= 1)
            part[h] += __shfl_down_sync(0xffffffffu, part[h], o);

    const int wid = tid >> 5, lane = tid & 31;
    if (lane == 0)
#pragma unroll
        for (int h = 0; h < HEADS; h++) red[wid][h] = part[h];
    __syncthreads();
    if (tid < HEADS) {
        float s = 0.f;
#pragma unroll
        for (int w = 0; w < 8; w++) s += red[w][tid];
        lin_s[tid] = s * gt[tid];
    }
    __syncthreads();
    float lin[HEADS];
#pragma unroll
    for (int h = 0; h < HEADS; h++) lin[h] = lin_s[h];

#pragma unroll
    for (int i = 0; i < DINNER / 256; i++) {
        const int j = tid + i * 256;
        float v = hidden[(size_t)t * DINNER + j];
#pragma unroll
        for (int h = 0; h < HEADS; h++)
            v = fmaf(lin[h], __ldg(&in_b[(size_t)id[h] * DINNER + j]), v);
        // exact gelu (erf form, matches jax approximate=False)
        v = 0.5f * v * (1.0f + erff(v * 0.70710678118654752f));
        hidden[(size_t)t * DINNER + j] = v;
    }
}

// ---------------------------------------------------------------------------
// Fuse 2: out[t] += sum_h gate*(hidden[t].out_a[i_h])*out_b[i_h]
// ---------------------------------------------------------------------------
__global__ __launch_bounds__(256) void fuse_out_kernel(
    const float* __restrict__ hidden, const float* __restrict__ out_a,
    const float* __restrict__ out_b, const int* __restrict__ idx,
    const float* __restrict__ gate, float* __restrict__ out)
{
    const int t = blockIdx.x;
    const int tid = threadIdx.x;
    __shared__ __align__(16) float hs[DINNER];
    __shared__ float red[8][HEADS];
    __shared__ float lin_s[HEADS];

    const float* hp = hidden + (size_t)t * DINNER;
    for (int i = tid; i < DINNER; i += 256) hs[i] = hp[i];

    int id[HEADS];
    float gt[HEADS];
#pragma unroll
    for (int h = 0; h < HEADS; h++) {
        id[h] = idx[t * HEADS + h];
        gt[h] = gate[t * HEADS + h];
    }
    __syncthreads();

    float part[HEADS];
#pragma unroll
    for (int h = 0; h < HEADS; h++) part[h] = 0.f;
#pragma unroll
    for (int i = 0; i < DINNER / 256; i++) {
        const int d = tid + i * 256;
        const float hv = hs[d];
#pragma unroll
        for (int h = 0; h < HEADS; h++)
            part[h] = fmaf(hv, __ldg(&out_a[(size_t)id[h] * DINNER + d]), part[h]);
    }
#pragma unroll
    for (int h = 0; h < HEADS; h++)
#pragma unroll
        for (int o = 16; o; o >>= 1)
            part[h] += __shfl_down_sync(0xffffffffu, part[h], o);

    const int wid = tid >> 5, lane = tid & 31;
    if (lane == 0)
#pragma unroll
        for (int h = 0; h < HEADS; h++) red[wid][h] = part[h];
    __syncthreads();
    if (tid < HEADS) {
        float s = 0.f;
#pragma unroll
        for (int w = 0; w < 8; w++) s += red[w][tid];
        lin_s[tid] = s * gt[tid];
    }
    __syncthreads();
    float lin[HEADS];
#pragma unroll
    for (int h = 0; h < HEADS; h++) lin[h] = lin_s[h];

#pragma unroll
    for (int i = 0; i < DIM / 256; i++) {
        const int j = tid + i * 256;
        float v = out[(size_t)t * DIM + j];
#pragma unroll
        for (int h = 0; h < HEADS; h++)
            v = fmaf(lin[h], __ldg(&out_b[(size_t)id[h] * DIM + j]), v);
        out[(size_t)t * DIM + j] = v;
    }
}

// ---------------------------------------------------------------------------
extern "C" void kernel_launch(void* const* d_in, const int* in_sizes, int n_in,
                              void* d_out, int out_size)
{
    const float* x     = (const float*)d_in[0];
    const float* Wq    = (const float*)d_in[1];
    const float* keys  = (const float*)d_in[2];
    const float* W_in  = (const float*)d_in[3];
    const float* W_out = (const float*)d_in[4];
    const float* in_a  = (const float*)d_in[5];
    const float* in_b  = (const float*)d_in[6];
    const float* out_a = (const float*)d_in[7];
    const float* out_b = (const float*)d_in[8];
    float* out = (float*)d_out;

    float *pM, *pSim, *pHid, *pGate;
    int* pIdx;
    cudaGetSymbolAddress((void**)&pM, g_M);
    cudaGetSymbolAddress((void**)&pSim, g_sim);
    cudaGetSymbolAddress((void**)&pHid, g_hid);
    cudaGetSymbolAddress((void**)&pIdx, g_idx);
    cudaGetSymbolAddress((void**)&pGate, g_gate);

    // K1: fold keys into Wq ->  M[(p,h,k), d], batched over z = p*8 + h.
    //   C_ph[k,d] = sum_dk keys[h,k,p,dk] * Wq[(p*8+h)*512 + dk, d]
    //   A = keys (+ p*512 + h*131072), lda = 1024 (k-rows)
    //   B = Wq (trans; B[j=d, kk=dk] at Wq[(base+kk)*1024 + d]), ldb = 1024
    //   C = g_M + z*131072, ldc = 1024
    gemm_tn<true><<<dim3(1024 / BN, 128 / BM, 16), 256>>>(
        keys, Wq, pM, 128, 1024, 512, 1024, 1024, 1024,
        /*zdiv=*/8,
        /*sah(p)=*/512, /*sal(h)=*/131072,
        /*sbh(p)=*/(size_t)8 * 524288, /*sbl(h)=*/524288,
        /*sch(p)=*/(size_t)8 * 131072, /*scl(h)=*/131072);

    // K2: sim = x @ M^T   [8192 x 2048]
    gemm_tn<false><<<dim3(2048 / BN, T_TOK / BM, 1), 256>>>(
        x, pM, pSim, T_TOK, 2048, 1024, 1024, 1024, 2048,
        1, 0, 0, 0, 0, 0, 0);

    // K3: per-(t,h) argmax pair -> idx, gate
    select_kernel<<<(T_TOK * HEADS * 32) / 256, 256>>>(pSim, pIdx, pGate);

    // K4: hidden_pre = x @ W_in^T   [8192 x 2048]
    gemm_tn<false><<<dim3(DINNER / BN, T_TOK / BM, 1), 256>>>(
        x, W_in, pHid, T_TOK, DINNER, 1024, 1024, 1024, DINNER,
        1, 0, 0, 0, 0, 0, 0);

    // K5: hidden = gelu(hidden_pre + expert-in contributions)
    fuse_in_kernel<<<T_TOK, 256>>>(x, in_a, in_b, pIdx, pGate, pHid);

    // K6: out = hidden @ W_out^T   [8192 x 1024]
    gemm_tn<false><<<dim3(DIM / BN, T_TOK / BM, 1), 256>>>(
        pHid, W_out, out, T_TOK, DIM, DINNER, DINNER, DINNER, DIM,
        1, 0, 0, 0, 0, 0, 0);

    // K7: out += expert-out contributions
    fuse_out_kernel<<<T_TOK, 256>>>(pHid, out_a, out_b, pIdx, pGate, out);
}

// round 6
// speedup vs baseline: 1.7180x; 1.7180x over previous
#include <cuda_runtime.h>
#include <cuda_bf16.h>
#include <math.h>
#include <cstdint>

// ---------------------------------------------------------------------------
// PEER-LoRA fused pipeline, round 6 (re-bench of R5 after infra failure).
// GEMMs: split-bf16 emulated-fp32 (a = a_hi + a_lo, 3x mma.sync m16n8k16),
// error ~2^-17 per element. Selection additionally re-scores in exact fp32
// when the top-2 gap is ambiguous (gap < 2e-4).
//   B=4,N=2048 -> T=8192 tokens, DIM=1024, HEADS=8, NUM_KEYS=128,
//   DIM_KEY=512, DIM_INNER=2048, TOPK=1.
// ---------------------------------------------------------------------------

#define T_TOK   8192
#define DIM     1024
#define DINNER  2048
#define HEADS   8
#define NKEYS   128

typedef __nv_bfloat16 bf16;

// fp32 scratch
__device__ __align__(128) float g_M[2048 * 1024];
__device__ __align__(128) float g_sim[T_TOK * 2048];
__device__ __align__(128) float g_hid[T_TOK * DINNER];
__device__ int   g_idx[T_TOK * HEADS];
__device__ float g_gate[T_TOK * HEADS];

// bf16 hi/lo split scratch
__device__ __align__(128) bf16 g_xhi[T_TOK * DIM],      g_xlo[T_TOK * DIM];
__device__ __align__(128) bf16 g_Mhi[2048 * 1024],      g_Mlo[2048 * 1024];
__device__ __align__(128) bf16 g_Qhi[16 * 1024 * 512],  g_Qlo[16 * 1024 * 512];
__device__ __align__(128) bf16 g_Khi[8 * 128 * 2 * 512], g_Klo[8 * 128 * 2 * 512];
__device__ __align__(128) bf16 g_WIhi[DINNER * DIM],    g_WIlo[DINNER * DIM];
__device__ __align__(128) bf16 g_WOhi[DIM * DINNER],    g_WOlo[DIM * DINNER];
__device__ __align__(128) bf16 g_Hhi[T_TOK * DINNER],   g_Hlo[T_TOK * DINNER];

// ============================ helpers ======================================
__device__ __forceinline__ uint32_t smem_u32(const void* p) {
    uint32_t a;
    asm("{ .reg .u64 t; cvta.to.shared.u64 t, %1; cvt.u32.u64 %0, t; }"
        : "=r"(a) : "l"(p));
    return a;
}
__device__ __forceinline__ void cpa16(uint32_t dst, const void* src) {
    asm volatile("cp.async.cg.shared.global [%0], [%1], 16;"
                 :: "r"(dst), "l"(src) : "memory");
}
__device__ __forceinline__ void ldmx4(uint32_t* r, uint32_t addr) {
    asm volatile("ldmatrix.sync.aligned.m8n8.x4.shared.b16 {%0,%1,%2,%3}, [%4];"
                 : "=r"(r[0]), "=r"(r[1]), "=r"(r[2]), "=r"(r[3]) : "r"(addr));
}
__device__ __forceinline__ void mma_bf16(float* d, const uint32_t* a,
                                         uint32_t b0, uint32_t b1) {
    asm volatile(
        "mma.sync.aligned.m16n8k16.row.col.f32.bf16.bf16.f32 "
        "{%0,%1,%2,%3}, {%4,%5,%6,%7}, {%8,%9}, {%0,%1,%2,%3};"
        : "+f"(d[0]), "+f"(d[1]), "+f"(d[2]), "+f"(d[3])
        : "r"(a[0]), "r"(a[1]), "r"(a[2]), "r"(a[3]), "r"(b0), "r"(b1));
}
// swizzled smem offset for a [128 rows x 32 bf16] tile stored as 64x128B atoms
__device__ __forceinline__ uint32_t swz(int row, int c) {
    return (uint32_t)(((row >> 1) * 128) +
                      ((((((row & 1) << 2) | c)) ^ ((row >> 1) & 7)) << 4));
}

// ======================= split-bf16 GEMM ===================================
// C[M,N] = A[M,K] @ B[N,K]^T with A,B given as (hi,lo) bf16 pairs.
// CTA tile 128x128x32, 8 warps (2x4), warp 64x32, double-buffered cp.async.
// Batched over blockIdx.z (zdiv/strides, element units).
#define STAGE_B 32768                 // 4 matrices x 8KB
#define GEMM_SMEM (2 * STAGE_B)

__global__ __launch_bounds__(256) void gemm_b2(
    const bf16* __restrict__ Ahi, const bf16* __restrict__ Alo,
    const bf16* __restrict__ Bhi, const bf16* __restrict__ Blo,
    float* __restrict__ Cb, int lda, int ldb, int ldc, int nk,
    int zdiv, size_t sah, size_t sal, size_t sbh, size_t sbl,
    size_t sch, size_t scl)
{
    extern __shared__ __align__(1024) char smem[];
    const int z = blockIdx.z;
    const int zh = z / zdiv, zl = z % zdiv;
    const size_t aoff = zh * sah + zl * sal;
    const size_t boff = zh * sbh + zl * sbl;
    float* C = Cb + zh * sch + zl * scl;

    const int tid  = threadIdx.x;
    const int wid  = tid >> 5, lane = tid & 31;
    const int m0   = blockIdx.y * 128;
    const int n0   = blockIdx.x * 128;
    const int m_off = (wid >> 2) * 64;
    const int n_off = (wid & 3) * 32;

    const uint32_t sbase = smem_u32(smem);

    // cp.async mapping: thread owns 16B chunks q=2*tid, 2*tid+1 of each matrix
    const int q0 = tid * 2;
    const int r0 = q0 >> 2, c0 = q0 & 3;          // chunk 0: row, col-chunk
    const int r1 = (q0 + 1) >> 2, c1 = (q0 + 1) & 3;
    const uint32_t so0 = swz(r0, c0), so1 = swz(r1, c1);
    const bf16* gah = Ahi + aoff + (size_t)(m0 + r0) * lda + c0 * 8;
    const bf16* gal = Alo + aoff + (size_t)(m0 + r0) * lda + c0 * 8;
    const bf16* gbh = Bhi + boff + (size_t)(n0 + r0) * ldb + c0 * 8;
    const bf16* gbl = Blo + boff + (size_t)(n0 + r0) * ldb + c0 * 8;
    const bf16* gah1 = Ahi + aoff + (size_t)(m0 + r1) * lda + c1 * 8;
    const bf16* gal1 = Alo + aoff + (size_t)(m0 + r1) * lda + c1 * 8;
    const bf16* gbh1 = Bhi + boff + (size_t)(n0 + r1) * ldb + c1 * 8;
    const bf16* gbl1 = Blo + boff + (size_t)(n0 + r1) * ldb + c1 * 8;

    auto load_tile = [&](int kt, int s) {
        const uint32_t b = sbase + s * STAGE_B;
        const int ke = kt * 32;
        cpa16(b + so0,         gah  + ke);
        cpa16(b + so1,         gah1 + ke);
        cpa16(b + 8192  + so0, gal  + ke);
        cpa16(b + 8192  + so1, gal1 + ke);
        cpa16(b + 16384 + so0, gbh  + ke);
        cpa16(b + 16384 + so1, gbh1 + ke);
        cpa16(b + 24576 + so0, gbl  + ke);
        cpa16(b + 24576 + so1, gbl1 + ke);
        asm volatile("cp.async.commit_group;" ::: "memory");
    };

    // ldmatrix base addresses (kh=0, mt/np=0)
    const int laneAr = lane & 15;
    const int laneAc = lane >> 4;                  // chunk bit0
    const uint32_t addrA = swz(m_off + laneAr, laneAc);
    const int laneBr = ((lane >> 4) << 3) + (lane & 7);
    const int laneBc = (lane >> 3) & 1;
    const uint32_t addrB = 16384 + swz(n_off + laneBr, laneBc);

    float acc[4][4][4];
#pragma unroll
    for (int i = 0; i < 4; i++)
#pragma unroll
        for (int j = 0; j < 4; j++)
#pragma unroll
            for (int r = 0; r < 4; r++) acc[i][j][r] = 0.f;

    load_tile(0, 0);

    for (int kt = 0; kt < nk; kt++) {
        const int s = kt & 1;
        if (kt + 1 < nk) {
            load_tile(kt + 1, s ^ 1);
            asm volatile("cp.async.wait_group 1;" ::: "memory");
        } else {
            asm volatile("cp.async.wait_group 0;" ::: "memory");
        }
        __syncthreads();

        const uint32_t sb = sbase + s * STAGE_B;
#pragma unroll
        for (int kh = 0; kh < 2; kh++) {
            const uint32_t kx = kh << 5;           // chunk bit1 -> addr bit5
            uint32_t ah[4][4], al[4][4], bh[2][4], bl[2][4];
#pragma unroll
            for (int mt = 0; mt < 4; mt++) {
                ldmx4(ah[mt], (sb + addrA + mt * 1024) ^ kx);
                ldmx4(al[mt], (sb + 8192 + addrA + mt * 1024) ^ kx);
            }
#pragma unroll
            for (int np = 0; np < 2; np++) {
                ldmx4(bh[np], (sb + 16384 + (addrB - 16384) + np * 1024) ^ kx);
                ldmx4(bl[np], (sb + 24576 + (addrB - 16384) + np * 1024) ^ kx);
            }
#pragma unroll
            for (int mt = 0; mt < 4; mt++)
#pragma unroll
                for (int nt = 0; nt < 4; nt++) {
                    const int np = nt >> 1, e = (nt & 1) * 2;
                    mma_bf16(acc[mt][nt], ah[mt], bh[np][e], bh[np][e + 1]);
                    mma_bf16(acc[mt][nt], ah[mt], bl[np][e], bl[np][e + 1]);
                    mma_bf16(acc[mt][nt], al[mt], bh[np][e], bh[np][e + 1]);
                }
        }
        __syncthreads();
    }

    const int lg = lane >> 2, lt = lane & 3;
#pragma unroll
    for (int mt = 0; mt < 4; mt++) {
        const int r = m0 + m_off + mt * 16 + lg;
#pragma unroll
        for (int nt = 0; nt < 4; nt++) {
            const int cc = n0 + n_off + nt * 8 + lt * 2;
            float2 v0 = {acc[mt][nt][0], acc[mt][nt][1]};
            float2 v1 = {acc[mt][nt][2], acc[mt][nt][3]};
            *(float2*)(C + (size_t)r * ldc + cc)       = v0;
            *(float2*)(C + (size_t)(r + 8) * ldc + cc) = v1;
        }
    }
}

// ===================== elementwise hi/lo split =============================
__global__ __launch_bounds__(256) void split_kernel(
    const float4* __restrict__ src, uint32_t* __restrict__ hi,
    uint32_t* __restrict__ lo, int n4)
{
    for (int i = blockIdx.x * blockDim.x + threadIdx.x; i < n4;
         i += gridDim.x * blockDim.x) {
        float4 v = src[i];
        bf16 h0 = __float2bfloat16(v.x), h1 = __float2bfloat16(v.y);
        bf16 h2 = __float2bfloat16(v.z), h3 = __float2bfloat16(v.w);
        bf16 l0 = __float2bfloat16(v.x - __bfloat162float(h0));
        bf16 l1 = __float2bfloat16(v.y - __bfloat162float(h1));
        bf16 l2 = __float2bfloat16(v.z - __bfloat162float(h2));
        bf16 l3 = __float2bfloat16(v.w - __bfloat162float(h3));
        __nv_bfloat162 H0 = {h0, h1}, H1 = {h2, h3};
        __nv_bfloat162 L0 = {l0, l1}, L1 = {l2, l3};
        hi[i * 2]     = *(uint32_t*)&H0;
        hi[i * 2 + 1] = *(uint32_t*)&H1;
        lo[i * 2]     = *(uint32_t*)&L0;
        lo[i * 2 + 1] = *(uint32_t*)&L1;
    }
}

// ============== Wq transpose + split: Wqt[z][d][dk] bf16 ===================
__global__ __launch_bounds__(256) void transpose_split_wq(
    const float* __restrict__ Wq, bf16* __restrict__ Qhi, bf16* __restrict__ Qlo)
{
    __shared__ float t[32][33];
    const int z = blockIdx.z;
    const int d0 = blockIdx.x * 32, dk0 = blockIdx.y * 32;
    const int tx = threadIdx.x, ty = threadIdx.y;
#pragma unroll
    for (int i = ty; i < 32; i += 8)
        t[i][tx] = Wq[(size_t)(z * 512 + dk0 + i) * 1024 + d0 + tx];
    __syncthreads();
#pragma unroll
    for (int i = ty; i < 32; i += 8) {
        float v = t[tx][i];
        bf16 h = __float2bfloat16(v);
        bf16 l = __float2bfloat16(v - __bfloat162float(h));
        size_t o = (size_t)z * 524288 + (size_t)(d0 + i) * 512 + dk0 + tx;
        Qhi[o] = h;
        Qlo[o] = l;
    }
}

// ========================== select =========================================
// One warp per (t,h). Per axis p: warp top-2 over 128 bf16x2 scores;
// exact fp32 re-score of the two candidates when the gap < TAU.
#define TAU 2e-4f
__global__ __launch_bounds__(256) void select_kernel(
    const float* __restrict__ sim, const float* __restrict__ x,
    const float* __restrict__ M, int* __restrict__ idx_out,
    float* __restrict__ gate_out)
{
    const int gw = (blockIdx.x * blockDim.x + threadIdx.x) >> 5;
    const int lane = threadIdx.x & 31;
    if (gw >= T_TOK * HEADS) return;
    const int t = gw >> 3;
    const int h = gw & 7;

    float win_v[2]; int win_i[2];
#pragma unroll
    for (int p = 0; p < 2; p++) {
        const float* s = sim + (size_t)t * 2048 + p * 1024 + h * 128;
        float v1 = -1e30f, v2 = -1e30f;
        int i1 = 0, i2 = 0;
#pragma unroll
        for (int u = 0; u < 4; u++) {
            const int k = lane + u * 32;
            const float v = s[k];
            if (v > v1 || (v == v1 && k < i1)) { v2 = v1; i2 = i1; v1 = v; i1 = k; }
            else if (v > v2 || (v == v2 && k < i2)) { v2 = v; i2 = k; }
        }
#pragma unroll
        for (int o = 16; o; o >>= 1) {
            float pv1 = __shfl_xor_sync(0xffffffffu, v1, o);
            int   pi1 = __shfl_xor_sync(0xffffffffu, i1, o);
            float pv2 = __shfl_xor_sync(0xffffffffu, v2, o);
            int   pi2 = __shfl_xor_sync(0xffffffffu, i2, o);
            if (pv1 > v1 || (pv1 == v1 && pi1 < i1)) {
                v2 = v1; i2 = i1; v1 = pv1; i1 = pi1;
            } else if (pv1 > v2 || (pv1 == v2 && pi1 < i2)) { v2 = pv1; i2 = pi1; }
            if (pv2 > v2 || (pv2 == v2 && pi2 < i2)) { v2 = pv2; i2 = pi2; }
        }
        if (v1 - v2 < TAU) {
            // exact fp32 re-score of both candidates
            const float* xr = x + (size_t)t * DIM;
            float e[2];
            int cand[2] = {i1, i2};
#pragma unroll
            for (int c = 0; c < 2; c++) {
                const float* mr = M + (size_t)(p * 1024 + h * 128 + cand[c]) * 1024;
                float sacc = 0.f;
                for (int d = lane; d < DIM; d += 32)
                    sacc = fmaf(xr[d], mr[d], sacc);
#pragma unroll
                for (int o = 16; o; o >>= 1)
                    sacc += __shfl_xor_sync(0xffffffffu, sacc, o);
                e[c] = sacc;
            }
            if (e[1] > e[0] || (e[1] == e[0] && i2 < i1)) {
                win_v[p] = e[1]; win_i[p] = i2;
            } else { win_v[p] = e[0]; win_i[p] = i1; }
        } else {
            win_v[p] = v1; win_i[p] = i1;
        }
    }
    if (lane == 0) {
        const float sc = win_v[0] + win_v[1];
        gate_out[gw] = sc > 0.f ? sc : 0.f;
        idx_out[gw] = win_i[0] * NKEYS + win_i[1];
    }
}

// ====================== fuse kernels =======================================
__global__ __launch_bounds__(256) void fuse_in_kernel(
    const float* __restrict__ x, const float* __restrict__ in_a,
    const float* __restrict__ in_b, const int* __restrict__ idx,
    const float* __restrict__ gate, float* __restrict__ hidden)
{
    const int t = blockIdx.x;
    const int tid = threadIdx.x;
    __shared__ __align__(16) float xs[DIM];
    __shared__ float red[8][HEADS];
    __shared__ float lin_s[HEADS];

    const float* xp = x + (size_t)t * DIM;
    for (int i = tid; i < DIM; i += 256) xs[i] = xp[i];

    int id[HEADS]; float gt[HEADS];
#pragma unroll
    for (int h = 0; h < HEADS; h++) {
        id[h] = idx[t * HEADS + h];
        gt[h] = gate[t * HEADS + h];
    }
    __syncthreads();

    float part[HEADS];
#pragma unroll
    for (int h = 0; h < HEADS; h++) part[h] = 0.f;
#pragma unroll
    for (int i = 0; i < DIM / 256; i++) {
        const int d = tid + i * 256;
        const float xv = xs[d];
#pragma unroll
        for (int h = 0; h < HEADS; h++)
            part[h] = fmaf(xv, __ldg(&in_a[(size_t)id[h] * DIM + d]), part[h]);
    }
#pragma unroll
    for (int h = 0; h < HEADS; h++)
#pragma unroll
        for (int o = 16; o; o >>= 1)
            part[h] += __shfl_down_sync(0xffffffffu, part[h], o);

    const int wid = tid >> 5, lane = tid & 31;
    if (lane == 0)
#pragma unroll
        for (int h = 0; h < HEADS; h++) red[wid][h] = part[h];
    __syncthreads();
    if (tid < HEADS) {
        float s = 0.f;
#pragma unroll
        for (int w = 0; w < 8; w++) s += red[w][tid];
        lin_s[tid] = s * gt[tid];
    }
    __syncthreads();
    float lin[HEADS];
#pragma unroll
    for (int h = 0; h < HEADS; h++) lin[h] = lin_s[h];

#pragma unroll
    for (int i = 0; i < DINNER / 256; i++) {
        const int j = tid + i * 256;
        float v = hidden[(size_t)t * DINNER + j];
#pragma unroll
        for (int h = 0; h < HEADS; h++)
            v = fmaf(lin[h], __ldg(&in_b[(size_t)id[h] * DINNER + j]), v);
        v = 0.5f * v * (1.0f + erff(v * 0.70710678118654752f));
        hidden[(size_t)t * DINNER + j] = v;
    }
}

__global__ __launch_bounds__(256) void fuse_out_kernel(
    const float* __restrict__ hidden, const float* __restrict__ out_a,
    const float* __restrict__ out_b, const int* __restrict__ idx,
    const float* __restrict__ gate, float* __restrict__ out)
{
    const int t = blockIdx.x;
    const int tid = threadIdx.x;
    __shared__ __align__(16) float hs[DINNER];
    __shared__ float red[8][HEADS];
    __shared__ float lin_s[HEADS];

    const float* hp = hidden + (size_t)t * DINNER;
    for (int i = tid; i < DINNER; i += 256) hs[i] = hp[i];

    int id[HEADS]; float gt[HEADS];
#pragma unroll
    for (int h = 0; h < HEADS; h++) {
        id[h] = idx[t * HEADS + h];
        gt[h] = gate[t * HEADS + h];
    }
    __syncthreads();

    float part[HEADS];
#pragma unroll
    for (int h = 0; h < HEADS; h++) part[h] = 0.f;
#pragma unroll
    for (int i = 0; i < DINNER / 256; i++) {
        const int d = tid + i * 256;
        const float hv = hs[d];
#pragma unroll
        for (int h = 0; h < HEADS; h++)
            part[h] = fmaf(hv, __ldg(&out_a[(size_t)id[h] * DINNER + d]), part[h]);
    }
#pragma unroll
    for (int h = 0; h < HEADS; h++)
#pragma unroll
        for (int o = 16; o; o >>= 1)
            part[h] += __shfl_down_sync(0xffffffffu, part[h], o);

    const int wid = tid >> 5, lane = tid & 31;
    if (lane == 0)
#pragma unroll
        for (int h = 0; h < HEADS; h++) red[wid][h] = part[h];
    __syncthreads();
    if (tid < HEADS) {
        float s = 0.f;
#pragma unroll
        for (int w = 0; w < 8; w++) s += red[w][tid];
        lin_s[tid] = s * gt[tid];
    }
    __syncthreads();
    float lin[HEADS];
#pragma unroll
    for (int h = 0; h < HEADS; h++) lin[h] = lin_s[h];

#pragma unroll
    for (int i = 0; i < DIM / 256; i++) {
        const int j = tid + i * 256;
        float v = out[(size_t)t * DIM + j];
#pragma unroll
        for (int h = 0; h < HEADS; h++)
            v = fmaf(lin[h], __ldg(&out_b[(size_t)id[h] * DIM + j]), v);
        out[(size_t)t * DIM + j] = v;
    }
}

// ===========================================================================
extern "C" void kernel_launch(void* const* d_in, const int* in_sizes, int n_in,
                              void* d_out, int out_size)
{
    const float* x     = (const float*)d_in[0];
    const float* Wq    = (const float*)d_in[1];
    const float* keys  = (const float*)d_in[2];
    const float* W_in  = (const float*)d_in[3];
    const float* W_out = (const float*)d_in[4];
    const float* in_a  = (const float*)d_in[5];
    const float* in_b  = (const float*)d_in[6];
    const float* out_a = (const float*)d_in[7];
    const float* out_b = (const float*)d_in[8];
    float* out = (float*)d_out;

    float *pM, *pSim, *pHid, *pGate;
    int* pIdx;
    bf16 *pXhi, *pXlo, *pMhi, *pMlo, *pQhi, *pQlo, *pKhi, *pKlo;
    bf16 *pWIhi, *pWIlo, *pWOhi, *pWOlo, *pHhi, *pHlo;
    cudaGetSymbolAddress((void**)&pM, g_M);
    cudaGetSymbolAddress((void**)&pSim, g_sim);
    cudaGetSymbolAddress((void**)&pHid, g_hid);
    cudaGetSymbolAddress((void**)&pIdx, g_idx);
    cudaGetSymbolAddress((void**)&pGate, g_gate);
    cudaGetSymbolAddress((void**)&pXhi, g_xhi);
    cudaGetSymbolAddress((void**)&pXlo, g_xlo);
    cudaGetSymbolAddress((void**)&pMhi, g_Mhi);
    cudaGetSymbolAddress((void**)&pMlo, g_Mlo);
    cudaGetSymbolAddress((void**)&pQhi, g_Qhi);
    cudaGetSymbolAddress((void**)&pQlo, g_Qlo);
    cudaGetSymbolAddress((void**)&pKhi, g_Khi);
    cudaGetSymbolAddress((void**)&pKlo, g_Klo);
    cudaGetSymbolAddress((void**)&pWIhi, g_WIhi);
    cudaGetSymbolAddress((void**)&pWIlo, g_WIlo);
    cudaGetSymbolAddress((void**)&pWOhi, g_WOhi);
    cudaGetSymbolAddress((void**)&pWOlo, g_WOlo);
    cudaGetSymbolAddress((void**)&pHhi, g_Hhi);
    cudaGetSymbolAddress((void**)&pHlo, g_Hlo);

    static bool attr_done = false;
    if (!attr_done) {
        cudaFuncSetAttribute(gemm_b2, cudaFuncAttributeMaxDynamicSharedMemorySize,
                             GEMM_SMEM);
        attr_done = true;
    }

    // --- prepasses: hi/lo splits (independent, memory-bound) ---
    split_kernel<<<1024, 256>>>((const float4*)x, (uint32_t*)pXhi,
                                (uint32_t*)pXlo, T_TOK * DIM / 4);
    split_kernel<<<512, 256>>>((const float4*)keys, (uint32_t*)pKhi,
                               (uint32_t*)pKlo, 8 * 128 * 2 * 512 / 4);
    split_kernel<<<512, 256>>>((const float4*)W_in, (uint32_t*)pWIhi,
                               (uint32_t*)pWIlo, DINNER * DIM / 4);
    split_kernel<<<512, 256>>>((const float4*)W_out, (uint32_t*)pWOhi,
                               (uint32_t*)pWOlo, DIM * DINNER / 4);
    transpose_split_wq<<<dim3(32, 16, 16), dim3(32, 8)>>>(Wq, pQhi, pQlo);

    // K1: fold keys into Wqt -> M[(p,h,k), d].  z = p*8 + h.
    gemm_b2<<<dim3(1024 / 128, 1, 16), 256, GEMM_SMEM>>>(
        pKhi, pKlo, pQhi, pQlo, pM, 1024, 512, 1024, 512 / 32,
        8, 512, 131072, (size_t)8 * 524288, 524288,
        (size_t)8 * 131072, 131072);
    split_kernel<<<512, 256>>>((const float4*)pM, (uint32_t*)pMhi,
                               (uint32_t*)pMlo, 2048 * 1024 / 4);

    // K2: sim = x @ M^T   [8192 x 2048], K=1024
    gemm_b2<<<dim3(2048 / 128, T_TOK / 128, 1), 256, GEMM_SMEM>>>(
        pXhi, pXlo, pMhi, pMlo, pSim, 1024, 1024, 2048, 1024 / 32,
        1, 0, 0, 0, 0, 0, 0);

    // K3: top-1 pair per (t,h) with exact fp32 re-score on ambiguity
    select_kernel<<<(T_TOK * HEADS * 32) / 256, 256>>>(pSim, x, pM, pIdx, pGate);

    // K4: hidden_pre = x @ W_in^T  [8192 x 2048], K=1024
    gemm_b2<<<dim3(DINNER / 128, T_TOK / 128, 1), 256, GEMM_SMEM>>>(
        pXhi, pXlo, pWIhi, pWIlo, pHid, 1024, 1024, DINNER, 1024 / 32,
        1, 0, 0, 0, 0, 0, 0);

    // K5: hidden = gelu(hidden_pre + expert-in)
    fuse_in_kernel<<<T_TOK, 256>>>(x, in_a, in_b, pIdx, pGate, pHid);
    split_kernel<<<1024, 256>>>((const float4*)pHid, (uint32_t*)pHhi,
                                (uint32_t*)pHlo, T_TOK * DINNER / 4);

    // K6: out = hidden @ W_out^T  [8192 x 1024], K=2048
    gemm_b2<<<dim3(DIM / 128, T_TOK / 128, 1), 256, GEMM_SMEM>>>(
        pHhi, pHlo, pWOhi, pWOlo, out, DINNER, DINNER, DIM, DINNER / 32,
        1, 0, 0, 0, 0, 0, 0);

    // K7: out += expert-out
    fuse_out_kernel<<<T_TOK, 256>>>(pHid, out_a, out_b, pIdx, pGate, out);
}

// round 11
// speedup vs baseline: 2.0740x; 1.2072x over previous
#include <cuda_runtime.h>
#include <cuda_bf16.h>
#include <math.h>
#include <cstdint>

// ---------------------------------------------------------------------------
// PEER-LoRA fused pipeline, round 7.
// R6 (1502us) + occupancy-2 GEMM, fused hidden-split, float4 fuse gathers.
//   B=4,N=2048 -> T=8192 tokens, DIM=1024, HEADS=8, NUM_KEYS=128,
//   DIM_KEY=512, DIM_INNER=2048, TOPK=1.
// ---------------------------------------------------------------------------

#define T_TOK   8192
#define DIM     1024
#define DINNER  2048
#define HEADS   8
#define NKEYS   128

typedef __nv_bfloat16 bf16;

// fp32 scratch
__device__ __align__(128) float g_M[2048 * 1024];
__device__ __align__(128) float g_sim[T_TOK * 2048];
__device__ __align__(128) float g_hid[T_TOK * DINNER];
__device__ int   g_idx[T_TOK * HEADS];
__device__ float g_gate[T_TOK * HEADS];

// bf16 hi/lo split scratch
__device__ __align__(128) bf16 g_xhi[T_TOK * DIM],      g_xlo[T_TOK * DIM];
__device__ __align__(128) bf16 g_Mhi[2048 * 1024],      g_Mlo[2048 * 1024];
__device__ __align__(128) bf16 g_Qhi[16 * 1024 * 512],  g_Qlo[16 * 1024 * 512];
__device__ __align__(128) bf16 g_Khi[8 * 128 * 2 * 512], g_Klo[8 * 128 * 2 * 512];
__device__ __align__(128) bf16 g_WIhi[DINNER * DIM],    g_WIlo[DINNER * DIM];
__device__ __align__(128) bf16 g_WOhi[DIM * DINNER],    g_WOlo[DIM * DINNER];
__device__ __align__(128) bf16 g_Hhi[T_TOK * DINNER],   g_Hlo[T_TOK * DINNER];

// ============================ helpers ======================================
__device__ __forceinline__ uint32_t smem_u32(const void* p) {
    uint32_t a;
    asm("{ .reg .u64 t; cvta.to.shared.u64 t, %1; cvt.u32.u64 %0, t; }"
        : "=r"(a) : "l"(p));
    return a;
}
__device__ __forceinline__ void cpa16(uint32_t dst, const void* src) {
    asm volatile("cp.async.cg.shared.global [%0], [%1], 16;"
                 :: "r"(dst), "l"(src) : "memory");
}
__device__ __forceinline__ void ldmx4(uint32_t* r, uint32_t addr) {
    asm volatile("ldmatrix.sync.aligned.m8n8.x4.shared.b16 {%0,%1,%2,%3}, [%4];"
                 : "=r"(r[0]), "=r"(r[1]), "=r"(r[2]), "=r"(r[3]) : "r"(addr));
}
__device__ __forceinline__ void mma_bf16(float* d, const uint32_t* a,
                                         uint32_t b0, uint32_t b1) {
    asm volatile(
        "mma.sync.aligned.m16n8k16.row.col.f32.bf16.bf16.f32 "
        "{%0,%1,%2,%3}, {%4,%5,%6,%7}, {%8,%9}, {%0,%1,%2,%3};"
        : "+f"(d[0]), "+f"(d[1]), "+f"(d[2]), "+f"(d[3])
        : "r"(a[0]), "r"(a[1]), "r"(a[2]), "r"(a[3]), "r"(b0), "r"(b1));
}
// swizzled smem offset for a [128 rows x 32 bf16] tile stored as 64x128B atoms
__device__ __forceinline__ uint32_t swz(int row, int c) {
    return (uint32_t)(((row >> 1) * 128) +
                      ((((((row & 1) << 2) | c)) ^ ((row >> 1) & 7)) << 4));
}
// hi/lo split of a float into two bf16
__device__ __forceinline__ void split_f(float v, bf16& h, bf16& l) {
    h = __float2bfloat16(v);
    l = __float2bfloat16(v - __bfloat162float(h));
}

// ======================= split-bf16 GEMM ===================================
// C[M,N] = A[M,K] @ B[N,K]^T with A,B given as (hi,lo) bf16 pairs.
// CTA tile 128x128x32, 8 warps (2x4), warp 64x32, double-buffered cp.async.
// Occupancy 2 CTAs/SM (A-fragments loaded per-mt to keep regs < 128).
#define STAGE_B 32768                 // 4 matrices x 8KB
#define GEMM_SMEM (2 * STAGE_B)

__global__ __launch_bounds__(256, 2) void gemm_b2(
    const bf16* __restrict__ Ahi, const bf16* __restrict__ Alo,
    const bf16* __restrict__ Bhi, const bf16* __restrict__ Blo,
    float* __restrict__ Cb, int lda, int ldb, int ldc, int nk,
    int zdiv, size_t sah, size_t sal, size_t sbh, size_t sbl,
    size_t sch, size_t scl)
{
    extern __shared__ __align__(1024) char smem[];
    const int z = blockIdx.z;
    const int zh = z / zdiv, zl = z % zdiv;
    const size_t aoff = zh * sah + zl * sal;
    const size_t boff = zh * sbh + zl * sbl;
    float* C = Cb + zh * sch + zl * scl;

    const int tid  = threadIdx.x;
    const int wid  = tid >> 5, lane = tid & 31;
    const int m0   = blockIdx.y * 128;
    const int n0   = blockIdx.x * 128;
    const int m_off = (wid >> 2) * 64;
    const int n_off = (wid & 3) * 32;

    const uint32_t sbase = smem_u32(smem);

    // cp.async mapping: thread owns 16B chunks q=2*tid, 2*tid+1 of each matrix
    const int q0 = tid * 2;
    const int r0 = q0 >> 2, c0 = q0 & 3;
    const int r1 = (q0 + 1) >> 2, c1 = (q0 + 1) & 3;
    const uint32_t so0 = swz(r0, c0), so1 = swz(r1, c1);
    const bf16* gah  = Ahi + aoff + (size_t)(m0 + r0) * lda + c0 * 8;
    const bf16* gal  = Alo + aoff + (size_t)(m0 + r0) * lda + c0 * 8;
    const bf16* gbh  = Bhi + boff + (size_t)(n0 + r0) * ldb + c0 * 8;
    const bf16* gbl  = Blo + boff + (size_t)(n0 + r0) * ldb + c0 * 8;
    const bf16* gah1 = Ahi + aoff + (size_t)(m0 + r1) * lda + c1 * 8;
    const bf16* gal1 = Alo + aoff + (size_t)(m0 + r1) * lda + c1 * 8;
    const bf16* gbh1 = Bhi + boff + (size_t)(n0 + r1) * ldb + c1 * 8;
    const bf16* gbl1 = Blo + boff + (size_t)(n0 + r1) * ldb + c1 * 8;

    auto load_tile = [&](int kt, int s) {
        const uint32_t b = sbase + s * STAGE_B;
        const int ke = kt * 32;
        cpa16(b + so0,         gah  + ke);
        cpa16(b + so1,         gah1 + ke);
        cpa16(b + 8192  + so0, gal  + ke);
        cpa16(b + 8192  + so1, gal1 + ke);
        cpa16(b + 16384 + so0, gbh  + ke);
        cpa16(b + 16384 + so1, gbh1 + ke);
        cpa16(b + 24576 + so0, gbl  + ke);
        cpa16(b + 24576 + so1, gbl1 + ke);
        asm volatile("cp.async.commit_group;" ::: "memory");
    };

    // ldmatrix base addresses (kh=0, mt/np=0)
    const int laneAr = lane & 15;
    const int laneAc = lane >> 4;
    const uint32_t addrA = swz(m_off + laneAr, laneAc);
    const int laneBr = ((lane >> 4) << 3) + (lane & 7);
    const int laneBc = (lane >> 3) & 1;
    const uint32_t addrB = swz(n_off + laneBr, laneBc);

    float acc[4][4][4];
#pragma unroll
    for (int i = 0; i < 4; i++)
#pragma unroll
        for (int j = 0; j < 4; j++)
#pragma unroll
            for (int r = 0; r < 4; r++) acc[i][j][r] = 0.f;

    load_tile(0, 0);

    for (int kt = 0; kt < nk; kt++) {
        const int s = kt & 1;
        if (kt + 1 < nk) {
            load_tile(kt + 1, s ^ 1);
            asm volatile("cp.async.wait_group 1;" ::: "memory");
        } else {
            asm volatile("cp.async.wait_group 0;" ::: "memory");
        }
        __syncthreads();

        const uint32_t sb = sbase + s * STAGE_B;
#pragma unroll
        for (int kh = 0; kh < 2; kh++) {
            const uint32_t kx = kh << 5;
            uint32_t bh[2][4], bl[2][4];
#pragma unroll
            for (int np = 0; np < 2; np++) {
                ldmx4(bh[np], (sb + 16384 + addrB + np * 1024) ^ kx);
                ldmx4(bl[np], (sb + 24576 + addrB + np * 1024) ^ kx);
            }
#pragma unroll
            for (int mt = 0; mt < 4; mt++) {
                uint32_t ah[4], al[4];
                ldmx4(ah, (sb + addrA + mt * 1024) ^ kx);
                ldmx4(al, (sb + 8192 + addrA + mt * 1024) ^ kx);
#pragma unroll
                for (int nt = 0; nt < 4; nt++) {
                    const int np = nt >> 1, e = (nt & 1) * 2;
                    mma_bf16(acc[mt][nt], ah, bh[np][e], bh[np][e + 1]);
                    mma_bf16(acc[mt][nt], ah, bl[np][e], bl[np][e + 1]);
                    mma_bf16(acc[mt][nt], al, bh[np][e], bh[np][e + 1]);
                }
            }
        }
        __syncthreads();
    }

    const int lg = lane >> 2, lt = lane & 3;
#pragma unroll
    for (int mt = 0; mt < 4; mt++) {
        const int r = m0 + m_off + mt * 16 + lg;
#pragma unroll
        for (int nt = 0; nt < 4; nt++) {
            const int cc = n0 + n_off + nt * 8 + lt * 2;
            float2 v0 = {acc[mt][nt][0], acc[mt][nt][1]};
            float2 v1 = {acc[mt][nt][2], acc[mt][nt][3]};
            *(float2*)(C + (size_t)r * ldc + cc)       = v0;
            *(float2*)(C + (size_t)(r + 8) * ldc + cc) = v1;
        }
    }
}

// ===================== elementwise hi/lo split =============================
__global__ __launch_bounds__(256) void split_kernel(
    const float4* __restrict__ src, uint32_t* __restrict__ hi,
    uint32_t* __restrict__ lo, int n4)
{
    for (int i = blockIdx.x * blockDim.x + threadIdx.x; i < n4;
         i += gridDim.x * blockDim.x) {
        float4 v = src[i];
        bf16 h0, h1, h2, h3, l0, l1, l2, l3;
        split_f(v.x, h0, l0); split_f(v.y, h1, l1);
        split_f(v.z, h2, l2); split_f(v.w, h3, l3);
        __nv_bfloat162 H0 = {h0, h1}, H1 = {h2, h3};
        __nv_bfloat162 L0 = {l0, l1}, L1 = {l2, l3};
        hi[i * 2]     = *(uint32_t*)&H0;
        hi[i * 2 + 1] = *(uint32_t*)&H1;
        lo[i * 2]     = *(uint32_t*)&L0;
        lo[i * 2 + 1] = *(uint32_t*)&L1;
    }
}

// ============== Wq transpose + split: Wqt[z][d][dk] bf16 ===================
__global__ __launch_bounds__(256) void transpose_split_wq(
    const float* __restrict__ Wq, bf16* __restrict__ Qhi, bf16* __restrict__ Qlo)
{
    __shared__ float t[32][33];
    const int z = blockIdx.z;
    const int d0 = blockIdx.x * 32, dk0 = blockIdx.y * 32;
    const int tx = threadIdx.x, ty = threadIdx.y;
#pragma unroll
    for (int i = ty; i < 32; i += 8)
        t[i][tx] = Wq[(size_t)(z * 512 + dk0 + i) * 1024 + d0 + tx];
    __syncthreads();
#pragma unroll
    for (int i = ty; i < 32; i += 8) {
        float v = t[tx][i];
        bf16 h, l;
        split_f(v, h, l);
        size_t o = (size_t)z * 524288 + (size_t)(d0 + i) * 512 + dk0 + tx;
        Qhi[o] = h;
        Qlo[o] = l;
    }
}

// ========================== select =========================================
// One warp per (t,h). Per axis p: warp top-2 over 128 bf16x2 scores;
// exact fp32 re-score of the two candidates when the gap < TAU.
#define TAU 2e-4f
__global__ __launch_bounds__(256) void select_kernel(
    const float* __restrict__ sim, const float* __restrict__ x,
    const float* __restrict__ M, int* __restrict__ idx_out,
    float* __restrict__ gate_out)
{
    const int gw = (blockIdx.x * blockDim.x + threadIdx.x) >> 5;
    const int lane = threadIdx.x & 31;
    if (gw >= T_TOK * HEADS) return;
    const int t = gw >> 3;
    const int h = gw & 7;

    float win_v[2]; int win_i[2];
#pragma unroll
    for (int p = 0; p < 2; p++) {
        const float* s = sim + (size_t)t * 2048 + p * 1024 + h * 128;
        float v1 = -1e30f, v2 = -1e30f;
        int i1 = 0, i2 = 0;
#pragma unroll
        for (int u = 0; u < 4; u++) {
            const int k = lane + u * 32;
            const float v = s[k];
            if (v > v1 || (v == v1 && k < i1)) { v2 = v1; i2 = i1; v1 = v; i1 = k; }
            else if (v > v2 || (v == v2 && k < i2)) { v2 = v; i2 = k; }
        }
#pragma unroll
        for (int o = 16; o; o >>= 1) {
            float pv1 = __shfl_xor_sync(0xffffffffu, v1, o);
            int   pi1 = __shfl_xor_sync(0xffffffffu, i1, o);
            float pv2 = __shfl_xor_sync(0xffffffffu, v2, o);
            int   pi2 = __shfl_xor_sync(0xffffffffu, i2, o);
            if (pv1 > v1 || (pv1 == v1 && pi1 < i1)) {
                v2 = v1; i2 = i1; v1 = pv1; i1 = pi1;
            } else if (pv1 > v2 || (pv1 == v2 && pi1 < i2)) { v2 = pv1; i2 = pi1; }
            if (pv2 > v2 || (pv2 == v2 && pi2 < i2)) { v2 = pv2; i2 = pi2; }
        }
        if (v1 - v2 < TAU) {
            const float* xr = x + (size_t)t * DIM;
            float e[2];
            int cand[2] = {i1, i2};
#pragma unroll
            for (int c = 0; c < 2; c++) {
                const float* mr = M + (size_t)(p * 1024 + h * 128 + cand[c]) * 1024;
                float sacc = 0.f;
                for (int d = lane; d < DIM; d += 32)
                    sacc = fmaf(xr[d], mr[d], sacc);
#pragma unroll
                for (int o = 16; o; o >>= 1)
                    sacc += __shfl_xor_sync(0xffffffffu, sacc, o);
                e[c] = sacc;
            }
            if (e[1] > e[0] || (e[1] == e[0] && i2 < i1)) {
                win_v[p] = e[1]; win_i[p] = i2;
            } else { win_v[p] = e[0]; win_i[p] = i1; }
        } else {
            win_v[p] = v1; win_i[p] = i1;
        }
    }
    if (lane == 0) {
        const float sc = win_v[0] + win_v[1];
        gate_out[gw] = sc > 0.f ? sc : 0.f;
        idx_out[gw] = win_i[0] * NKEYS + win_i[1];
    }
}

// ====================== fuse kernels =======================================
// Fuse 1: hidden = gelu(hidden_pre + sum_h gate*(x.in_a)*in_b); also emits
// the bf16 hi/lo split of hidden for the following GEMM.
__global__ __launch_bounds__(256) void fuse_in_kernel(
    const float* __restrict__ x, const float* __restrict__ in_a,
    const float* __restrict__ in_b, const int* __restrict__ idx,
    const float* __restrict__ gate, float* __restrict__ hidden,
    uint32_t* __restrict__ Hhi, uint32_t* __restrict__ Hlo)
{
    const int t = blockIdx.x;
    const int tid = threadIdx.x;
    __shared__ __align__(16) float xs[DIM];
    __shared__ float red[8][HEADS];
    __shared__ float lin_s[HEADS];

    const float4* xp4 = (const float4*)(x + (size_t)t * DIM);
    ((float4*)xs)[tid] = xp4[tid];

    int id[HEADS]; float gt[HEADS];
#pragma unroll
    for (int h = 0; h < HEADS; h++) {
        id[h] = idx[t * HEADS + h];
        gt[h] = gate[t * HEADS + h];
    }
    __syncthreads();

    // dot(x, in_a[id_h]) with float4 streams
    const float4 xv = ((const float4*)xs)[tid];
    float part[HEADS];
#pragma unroll
    for (int h = 0; h < HEADS; h++) {
        const float4 av = __ldg((const float4*)&in_a[(size_t)id[h] * DIM] + tid);
        part[h] = xv.x * av.x + xv.y * av.y + xv.z * av.z + xv.w * av.w;
    }
#pragma unroll
    for (int h = 0; h < HEADS; h++)
#pragma unroll
        for (int o = 16; o; o >>= 1)
            part[h] += __shfl_down_sync(0xffffffffu, part[h], o);

    const int wid = tid >> 5, lane = tid & 31;
    if (lane == 0)
#pragma unroll
        for (int h = 0; h < HEADS; h++) red[wid][h] = part[h];
    __syncthreads();
    if (tid < HEADS) {
        float s = 0.f;
#pragma unroll
        for (int w = 0; w < 8; w++) s += red[w][tid];
        lin_s[tid] = s * gt[tid];
    }
    __syncthreads();
    float lin[HEADS];
#pragma unroll
    for (int h = 0; h < HEADS; h++) lin[h] = lin_s[h];

    // hidden update + gelu + hi/lo split (float4 over DINNER)
#pragma unroll
    for (int i = 0; i < DINNER / 4 / 256; i++) {
        const int j4 = tid + i * 256;
        float4 v = ((float4*)(hidden + (size_t)t * DINNER))[j4];
#pragma unroll
        for (int h = 0; h < HEADS; h++) {
            const float4 bv = __ldg((const float4*)&in_b[(size_t)id[h] * DINNER] + j4);
            v.x = fmaf(lin[h], bv.x, v.x);
            v.y = fmaf(lin[h], bv.y, v.y);
            v.z = fmaf(lin[h], bv.z, v.z);
            v.w = fmaf(lin[h], bv.w, v.w);
        }
        v.x = 0.5f * v.x * (1.0f + erff(v.x * 0.70710678118654752f));
        v.y = 0.5f * v.y * (1.0f + erff(v.y * 0.70710678118654752f));
        v.z = 0.5f * v.z * (1.0f + erff(v.z * 0.70710678118654752f));
        v.w = 0.5f * v.w * (1.0f + erff(v.w * 0.70710678118654752f));
        ((float4*)(hidden + (size_t)t * DINNER))[j4] = v;

        bf16 h0, h1, h2, h3, l0, l1, l2, l3;
        split_f(v.x, h0, l0); split_f(v.y, h1, l1);
        split_f(v.z, h2, l2); split_f(v.w, h3, l3);
        __nv_bfloat162 H0 = {h0, h1}, H1 = {h2, h3};
        __nv_bfloat162 L0 = {l0, l1}, L1 = {l2, l3};
        const size_t o2 = (size_t)t * (DINNER / 2) + j4 * 2;
        Hhi[o2]     = *(uint32_t*)&H0;
        Hhi[o2 + 1] = *(uint32_t*)&H1;
        Hlo[o2]     = *(uint32_t*)&L0;
        Hlo[o2 + 1] = *(uint32_t*)&L1;
    }
}

// Fuse 2: out += sum_h gate*(hidden.out_a)*out_b  (float4 streams)
__global__ __launch_bounds__(256) void fuse_out_kernel(
    const float* __restrict__ hidden, const float* __restrict__ out_a,
    const float* __restrict__ out_b, const int* __restrict__ idx,
    const float* __restrict__ gate, float* __restrict__ out)
{
    const int t = blockIdx.x;
    const int tid = threadIdx.x;
    __shared__ __align__(16) float hs[DINNER];
    __shared__ float red[8][HEADS];
    __shared__ float lin_s[HEADS];

    const float4* hp4 = (const float4*)(hidden + (size_t)t * DINNER);
    ((float4*)hs)[tid]       = hp4[tid];
    ((float4*)hs)[tid + 256] = hp4[tid + 256];

    int id[HEADS]; float gt[HEADS];
#pragma unroll
    for (int h = 0; h < HEADS; h++) {
        id[h] = idx[t * HEADS + h];
        gt[h] = gate[t * HEADS + h];
    }
    __syncthreads();

    float part[HEADS];
#pragma unroll
    for (int h = 0; h < HEADS; h++) part[h] = 0.f;
#pragma unroll
    for (int i = 0; i < DINNER / 4 / 256; i++) {
        const int d4 = tid + i * 256;
        const float4 hv = ((const float4*)hs)[d4];
#pragma unroll
        for (int h = 0; h < HEADS; h++) {
            const float4 av = __ldg((const float4*)&out_a[(size_t)id[h] * DINNER] + d4);
            part[h] += hv.x * av.x + hv.y * av.y + hv.z * av.z + hv.w * av.w;
        }
    }
#pragma unroll
    for (int h = 0; h < HEADS; h++)
#pragma unroll
        for (int o = 16; o; o >>= 1)
            part[h] += __shfl_down_sync(0xffffffffu, part[h], o);

    const int wid = tid >> 5, lane = tid & 31;
    if (lane == 0)
#pragma unroll
        for (int h = 0; h < HEADS; h++) red[wid][h] = part[h];
    __syncthreads();
    if (tid < HEADS) {
        float s = 0.f;
#pragma unroll
        for (int w = 0; w < 8; w++) s += red[w][tid];
        lin_s[tid] = s * gt[tid];
    }
    __syncthreads();
    float lin[HEADS];
#pragma unroll
    for (int h = 0; h < HEADS; h++) lin[h] = lin_s[h];

    {
        const int j4 = tid;
        float4 v = ((float4*)(out + (size_t)t * DIM))[j4];
#pragma unroll
        for (int h = 0; h < HEADS; h++) {
            const float4 bv = __ldg((const float4*)&out_b[(size_t)id[h] * DIM] + j4);
            v.x = fmaf(lin[h], bv.x, v.x);
            v.y = fmaf(lin[h], bv.y, v.y);
            v.z = fmaf(lin[h], bv.z, v.z);
            v.w = fmaf(lin[h], bv.w, v.w);
        }
        ((float4*)(out + (size_t)t * DIM))[j4] = v;
    }
}

// ===========================================================================
extern "C" void kernel_launch(void* const* d_in, const int* in_sizes, int n_in,
                              void* d_out, int out_size)
{
    const float* x     = (const float*)d_in[0];
    const float* Wq    = (const float*)d_in[1];
    const float* keys  = (const float*)d_in[2];
    const float* W_in  = (const float*)d_in[3];
    const float* W_out = (const float*)d_in[4];
    const float* in_a  = (const float*)d_in[5];
    const float* in_b  = (const float*)d_in[6];
    const float* out_a = (const float*)d_in[7];
    const float* out_b = (const float*)d_in[8];
    float* out = (float*)d_out;

    float *pM, *pSim, *pHid, *pGate;
    int* pIdx;
    bf16 *pXhi, *pXlo, *pMhi, *pMlo, *pQhi, *pQlo, *pKhi, *pKlo;
    bf16 *pWIhi, *pWIlo, *pWOhi, *pWOlo, *pHhi, *pHlo;
    cudaGetSymbolAddress((void**)&pM, g_M);
    cudaGetSymbolAddress((void**)&pSim, g_sim);
    cudaGetSymbolAddress((void**)&pHid, g_hid);
    cudaGetSymbolAddress((void**)&pIdx, g_idx);
    cudaGetSymbolAddress((void**)&pGate, g_gate);
    cudaGetSymbolAddress((void**)&pXhi, g_xhi);
    cudaGetSymbolAddress((void**)&pXlo, g_xlo);
    cudaGetSymbolAddress((void**)&pMhi, g_Mhi);
    cudaGetSymbolAddress((void**)&pMlo, g_Mlo);
    cudaGetSymbolAddress((void**)&pQhi, g_Qhi);
    cudaGetSymbolAddress((void**)&pQlo, g_Qlo);
    cudaGetSymbolAddress((void**)&pKhi, g_Khi);
    cudaGetSymbolAddress((void**)&pKlo, g_Klo);
    cudaGetSymbolAddress((void**)&pWIhi, g_WIhi);
    cudaGetSymbolAddress((void**)&pWIlo, g_WIlo);
    cudaGetSymbolAddress((void**)&pWOhi, g_WOhi);
    cudaGetSymbolAddress((void**)&pWOlo, g_WOlo);
    cudaGetSymbolAddress((void**)&pHhi, g_Hhi);
    cudaGetSymbolAddress((void**)&pHlo, g_Hlo);

    static bool attr_done = false;
    if (!attr_done) {
        cudaFuncSetAttribute(gemm_b2, cudaFuncAttributeMaxDynamicSharedMemorySize,
                             GEMM_SMEM);
        attr_done = true;
    }

    // --- prepasses: hi/lo splits ---
    split_kernel<<<1024, 256>>>((const float4*)x, (uint32_t*)pXhi,
                                (uint32_t*)pXlo, T_TOK * DIM / 4);
    split_kernel<<<512, 256>>>((const float4*)keys, (uint32_t*)pKhi,
                               (uint32_t*)pKlo, 8 * 128 * 2 * 512 / 4);
    split_kernel<<<512, 256>>>((const float4*)W_in, (uint32_t*)pWIhi,
                               (uint32_t*)pWIlo, DINNER * DIM / 4);
    split_kernel<<<512, 256>>>((const float4*)W_out, (uint32_t*)pWOhi,
                               (uint32_t*)pWOlo, DIM * DINNER / 4);
    transpose_split_wq<<<dim3(32, 16, 16), dim3(32, 8)>>>(Wq, pQhi, pQlo);

    // K1: fold keys into Wqt -> M[(p,h,k), d].  z = p*8 + h.
    gemm_b2<<<dim3(1024 / 128, 1, 16), 256, GEMM_SMEM>>>(
        pKhi, pKlo, pQhi, pQlo, pM, 1024, 512, 1024, 512 / 32,
        8, 512, 131072, (size_t)8 * 524288, 524288,
        (size_t)8 * 131072, 131072);
    split_kernel<<<512, 256>>>((const float4*)pM, (uint32_t*)pMhi,
                               (uint32_t*)pMlo, 2048 * 1024 / 4);

    // K2: sim = x @ M^T   [8192 x 2048], K=1024
    gemm_b2<<<dim3(2048 / 128, T_TOK / 128, 1), 256, GEMM_SMEM>>>(
        pXhi, pXlo, pMhi, pMlo, pSim, 1024, 1024, 2048, 1024 / 32,
        1, 0, 0, 0, 0, 0, 0);

    // K3: top-1 pair per (t,h) with exact fp32 re-score on ambiguity
    select_kernel<<<(T_TOK * HEADS * 32) / 256, 256>>>(pSim, x, pM, pIdx, pGate);

    // K4: hidden_pre = x @ W_in^T  [8192 x 2048], K=1024
    gemm_b2<<<dim3(DINNER / 128, T_TOK / 128, 1), 256, GEMM_SMEM>>>(
        pXhi, pXlo, pWIhi, pWIlo, pHid, 1024, 1024, DINNER, 1024 / 32,
        1, 0, 0, 0, 0, 0, 0);

    // K5: hidden = gelu(hidden_pre + expert-in), emits hi/lo split
    fuse_in_kernel<<<T_TOK, 256>>>(x, in_a, in_b, pIdx, pGate, pHid,
                                   (uint32_t*)pHhi, (uint32_t*)pHlo);

    // K6: out = hidden @ W_out^T  [8192 x 1024], K=2048
    gemm_b2<<<dim3(DIM / 128, T_TOK / 128, 1), 256, GEMM_SMEM>>>(
        pHhi, pHlo, pWOhi, pWOlo, out, DINNER, DINNER, DIM, DINNER / 32,
        1, 0, 0, 0, 0, 0, 0);

    // K7: out += expert-out
    fuse_out_kernel<<<T_TOK, 256>>>(pHid, out_a, out_b, pIdx, pGate, out);
}

// round 12
// speedup vs baseline: 2.1219x; 1.0231x over previous
#include <cuda_runtime.h>
#include <cuda_bf16.h>
#include <math.h>
#include <cstdint>

// ---------------------------------------------------------------------------
// PEER-LoRA fused pipeline, round 12.
// R11 (1244us) + 3-stage cp.async GEMM pipeline + merged sim/W_in GEMM
// (shared A in L2, one launch tail).
//   B=4,N=2048 -> T=8192 tokens, DIM=1024, HEADS=8, NUM_KEYS=128,
//   DIM_KEY=512, DIM_INNER=2048, TOPK=1.
// ---------------------------------------------------------------------------

#define T_TOK   8192
#define DIM     1024
#define DINNER  2048
#define HEADS   8
#define NKEYS   128

typedef __nv_bfloat16 bf16;

// fp32 scratch
__device__ __align__(128) float g_M[2048 * 1024];          // folded keys (fp32, for re-score)
__device__ __align__(128) float g_SH[2u * T_TOK * 2048];   // [0]=sim, [1]=hidden
__device__ int   g_idx[T_TOK * HEADS];
__device__ float g_gate[T_TOK * HEADS];

// bf16 hi/lo split scratch
__device__ __align__(128) bf16 g_xhi[T_TOK * DIM],      g_xlo[T_TOK * DIM];
__device__ __align__(128) bf16 g_BKWhi[2u * 2048 * 1024], g_BKWlo[2u * 2048 * 1024]; // [0]=M, [1]=W_in
__device__ __align__(128) bf16 g_Qhi[16 * 1024 * 512],  g_Qlo[16 * 1024 * 512];
__device__ __align__(128) bf16 g_Khi[8 * 128 * 2 * 512], g_Klo[8 * 128 * 2 * 512];
__device__ __align__(128) bf16 g_WOhi[DIM * DINNER],    g_WOlo[DIM * DINNER];
__device__ __align__(128) bf16 g_Hhi[T_TOK * DINNER],   g_Hlo[T_TOK * DINNER];

// ============================ helpers ======================================
__device__ __forceinline__ uint32_t smem_u32(const void* p) {
    uint32_t a;
    asm("{ .reg .u64 t; cvta.to.shared.u64 t, %1; cvt.u32.u64 %0, t; }"
        : "=r"(a) : "l"(p));
    return a;
}
__device__ __forceinline__ void cpa16(uint32_t dst, const void* src) {
    asm volatile("cp.async.cg.shared.global [%0], [%1], 16;"
                 :: "r"(dst), "l"(src) : "memory");
}
__device__ __forceinline__ void ldmx4(uint32_t* r, uint32_t addr) {
    asm volatile("ldmatrix.sync.aligned.m8n8.x4.shared.b16 {%0,%1,%2,%3}, [%4];"
                 : "=r"(r[0]), "=r"(r[1]), "=r"(r[2]), "=r"(r[3]) : "r"(addr));
}
__device__ __forceinline__ void mma_bf16(float* d, const uint32_t* a,
                                         uint32_t b0, uint32_t b1) {
    asm volatile(
        "mma.sync.aligned.m16n8k16.row.col.f32.bf16.bf16.f32 "
        "{%0,%1,%2,%3}, {%4,%5,%6,%7}, {%8,%9}, {%0,%1,%2,%3};"
        : "+f"(d[0]), "+f"(d[1]), "+f"(d[2]), "+f"(d[3])
        : "r"(a[0]), "r"(a[1]), "r"(a[2]), "r"(a[3]), "r"(b0), "r"(b1));
}
// swizzled smem offset for a [128 rows x 32 bf16] tile stored as 64x128B atoms
__device__ __forceinline__ uint32_t swz(int row, int c) {
    return (uint32_t)(((row >> 1) * 128) +
                      ((((((row & 1) << 2) | c)) ^ ((row >> 1) & 7)) << 4));
}
// hi/lo split of a float into two bf16
__device__ __forceinline__ void split_f(float v, bf16& h, bf16& l) {
    h = __float2bfloat16(v);
    l = __float2bfloat16(v - __bfloat162float(h));
}

// ======================= split-bf16 GEMM ===================================
// C[M,N] = A[M,K] @ B[N,K]^T with A,B given as (hi,lo) bf16 pairs.
// CTA tile 128x128x32, 8 warps (2x4), warp 64x32, 3-stage cp.async ring.
// 2 CTAs/SM. Batched over blockIdx.z (zdiv/strides, element units).
#define STAGE_B 32768                 // 4 matrices x 8KB
#define GSTAGES 3
#define GEMM_SMEM (GSTAGES * STAGE_B) // 98304

__global__ __launch_bounds__(256, 2) void gemm_b2(
    const bf16* __restrict__ Ahi, const bf16* __restrict__ Alo,
    const bf16* __restrict__ Bhi, const bf16* __restrict__ Blo,
    float* __restrict__ Cb, int lda, int ldb, int ldc, int nk,
    int zdiv, size_t sah, size_t sal, size_t sbh, size_t sbl,
    size_t sch, size_t scl)
{
    extern __shared__ __align__(1024) char smem[];
    const int z = blockIdx.z;
    const int zh = z / zdiv, zl = z % zdiv;
    const size_t aoff = zh * sah + zl * sal;
    const size_t boff = zh * sbh + zl * sbl;
    float* C = Cb + zh * sch + zl * scl;

    const int tid  = threadIdx.x;
    const int wid  = tid >> 5, lane = tid & 31;
    const int m0   = blockIdx.y * 128;
    const int n0   = blockIdx.x * 128;
    const int m_off = (wid >> 2) * 64;
    const int n_off = (wid & 3) * 32;

    const uint32_t sbase = smem_u32(smem);

    // cp.async mapping: thread owns 16B chunks q=2*tid, 2*tid+1 of each matrix
    const int q0 = tid * 2;
    const int r0 = q0 >> 2, c0 = q0 & 3;
    const int r1 = (q0 + 1) >> 2, c1 = (q0 + 1) & 3;
    const uint32_t so0 = swz(r0, c0), so1 = swz(r1, c1);
    const bf16* gah  = Ahi + aoff + (size_t)(m0 + r0) * lda + c0 * 8;
    const bf16* gal  = Alo + aoff + (size_t)(m0 + r0) * lda + c0 * 8;
    const bf16* gbh  = Bhi + boff + (size_t)(n0 + r0) * ldb + c0 * 8;
    const bf16* gbl  = Blo + boff + (size_t)(n0 + r0) * ldb + c0 * 8;
    const bf16* gah1 = Ahi + aoff + (size_t)(m0 + r1) * lda + c1 * 8;
    const bf16* gal1 = Alo + aoff + (size_t)(m0 + r1) * lda + c1 * 8;
    const bf16* gbh1 = Bhi + boff + (size_t)(n0 + r1) * ldb + c1 * 8;
    const bf16* gbl1 = Blo + boff + (size_t)(n0 + r1) * ldb + c1 * 8;

    auto load_tile = [&](int kt) {
        const uint32_t b = sbase + (kt % GSTAGES) * STAGE_B;
        const int ke = kt * 32;
        cpa16(b + so0,         gah  + ke);
        cpa16(b + so1,         gah1 + ke);
        cpa16(b + 8192  + so0, gal  + ke);
        cpa16(b + 8192  + so1, gal1 + ke);
        cpa16(b + 16384 + so0, gbh  + ke);
        cpa16(b + 16384 + so1, gbh1 + ke);
        cpa16(b + 24576 + so0, gbl  + ke);
        cpa16(b + 24576 + so1, gbl1 + ke);
        asm volatile("cp.async.commit_group;" ::: "memory");
    };

    // ldmatrix base addresses
    const int laneAr = lane & 15;
    const int laneAc = lane >> 4;
    const uint32_t addrA = swz(m_off + laneAr, laneAc);
    const int laneBr = ((lane >> 4) << 3) + (lane & 7);
    const int laneBc = (lane >> 3) & 1;
    const uint32_t addrB = swz(n_off + laneBr, laneBc);

    float acc[4][4][4];
#pragma unroll
    for (int i = 0; i < 4; i++)
#pragma unroll
        for (int j = 0; j < 4; j++)
#pragma unroll
            for (int r = 0; r < 4; r++) acc[i][j][r] = 0.f;

    load_tile(0);
    if (nk > 1) load_tile(1);

    for (int kt = 0; kt < nk; kt++) {
        // issue load kt+2 (its stage was consumed at kt-1, synced at end of kt-1)
        if (kt + 2 < nk) {
            load_tile(kt + 2);
            asm volatile("cp.async.wait_group 2;" ::: "memory");
        } else if (kt + 1 < nk) {
            asm volatile("cp.async.wait_group 1;" ::: "memory");
        } else {
            asm volatile("cp.async.wait_group 0;" ::: "memory");
        }
        __syncthreads();

        const uint32_t sb = sbase + (kt % GSTAGES) * STAGE_B;
#pragma unroll
        for (int kh = 0; kh < 2; kh++) {
            const uint32_t kx = kh << 5;
            uint32_t bh[2][4], bl[2][4];
#pragma unroll
            for (int np = 0; np < 2; np++) {
                ldmx4(bh[np], (sb + 16384 + addrB + np * 1024) ^ kx);
                ldmx4(bl[np], (sb + 24576 + addrB + np * 1024) ^ kx);
            }
#pragma unroll
            for (int mt = 0; mt < 4; mt++) {
                uint32_t ah[4], al[4];
                ldmx4(ah, (sb + addrA + mt * 1024) ^ kx);
                ldmx4(al, (sb + 8192 + addrA + mt * 1024) ^ kx);
#pragma unroll
                for (int nt = 0; nt < 4; nt++) {
                    const int np = nt >> 1, e = (nt & 1) * 2;
                    mma_bf16(acc[mt][nt], ah, bh[np][e], bh[np][e + 1]);
                    mma_bf16(acc[mt][nt], ah, bl[np][e], bl[np][e + 1]);
                    mma_bf16(acc[mt][nt], al, bh[np][e], bh[np][e + 1]);
                }
            }
        }
        __syncthreads();
    }

    const int lg = lane >> 2, lt = lane & 3;
#pragma unroll
    for (int mt = 0; mt < 4; mt++) {
        const int r = m0 + m_off + mt * 16 + lg;
#pragma unroll
        for (int nt = 0; nt < 4; nt++) {
            const int cc = n0 + n_off + nt * 8 + lt * 2;
            float2 v0 = {acc[mt][nt][0], acc[mt][nt][1]};
            float2 v1 = {acc[mt][nt][2], acc[mt][nt][3]};
            *(float2*)(C + (size_t)r * ldc + cc)       = v0;
            *(float2*)(C + (size_t)(r + 8) * ldc + cc) = v1;
        }
    }
}

// ===================== elementwise hi/lo split =============================
__global__ __launch_bounds__(256) void split_kernel(
    const float4* __restrict__ src, uint32_t* __restrict__ hi,
    uint32_t* __restrict__ lo, int n4)
{
    for (int i = blockIdx.x * blockDim.x + threadIdx.x; i < n4;
         i += gridDim.x * blockDim.x) {
        float4 v = src[i];
        bf16 h0, h1, h2, h3, l0, l1, l2, l3;
        split_f(v.x, h0, l0); split_f(v.y, h1, l1);
        split_f(v.z, h2, l2); split_f(v.w, h3, l3);
        __nv_bfloat162 H0 = {h0, h1}, H1 = {h2, h3};
        __nv_bfloat162 L0 = {l0, l1}, L1 = {l2, l3};
        hi[i * 2]     = *(uint32_t*)&H0;
        hi[i * 2 + 1] = *(uint32_t*)&H1;
        lo[i * 2]     = *(uint32_t*)&L0;
        lo[i * 2 + 1] = *(uint32_t*)&L1;
    }
}

// ============== Wq transpose + split: Wqt[z][d][dk] bf16 ===================
__global__ __launch_bounds__(256) void transpose_split_wq(
    const float* __restrict__ Wq, bf16* __restrict__ Qhi, bf16* __restrict__ Qlo)
{
    __shared__ float t[32][33];
    const int z = blockIdx.z;
    const int d0 = blockIdx.x * 32, dk0 = blockIdx.y * 32;
    const int tx = threadIdx.x, ty = threadIdx.y;
#pragma unroll
    for (int i = ty; i < 32; i += 8)
        t[i][tx] = Wq[(size_t)(z * 512 + dk0 + i) * 1024 + d0 + tx];
    __syncthreads();
#pragma unroll
    for (int i = ty; i < 32; i += 8) {
        float v = t[tx][i];
        bf16 h, l;
        split_f(v, h, l);
        size_t o = (size_t)z * 524288 + (size_t)(d0 + i) * 512 + dk0 + tx;
        Qhi[o] = h;
        Qlo[o] = l;
    }
}

// ========================== select =========================================
#define TAU 2e-4f
__global__ __launch_bounds__(256) void select_kernel(
    const float* __restrict__ sim, const float* __restrict__ x,
    const float* __restrict__ M, int* __restrict__ idx_out,
    float* __restrict__ gate_out)
{
    const int gw = (blockIdx.x * blockDim.x + threadIdx.x) >> 5;
    const int lane = threadIdx.x & 31;
    if (gw >= T_TOK * HEADS) return;
    const int t = gw >> 3;
    const int h = gw & 7;

    float win_v[2]; int win_i[2];
#pragma unroll
    for (int p = 0; p < 2; p++) {
        const float* s = sim + (size_t)t * 2048 + p * 1024 + h * 128;
        float v1 = -1e30f, v2 = -1e30f;
        int i1 = 0, i2 = 0;
#pragma unroll
        for (int u = 0; u < 4; u++) {
            const int k = lane + u * 32;
            const float v = s[k];
            if (v > v1 || (v == v1 && k < i1)) { v2 = v1; i2 = i1; v1 = v; i1 = k; }
            else if (v > v2 || (v == v2 && k < i2)) { v2 = v; i2 = k; }
        }
#pragma unroll
        for (int o = 16; o; o >>= 1) {
            float pv1 = __shfl_xor_sync(0xffffffffu, v1, o);
            int   pi1 = __shfl_xor_sync(0xffffffffu, i1, o);
            float pv2 = __shfl_xor_sync(0xffffffffu, v2, o);
            int   pi2 = __shfl_xor_sync(0xffffffffu, i2, o);
            if (pv1 > v1 || (pv1 == v1 && pi1 < i1)) {
                v2 = v1; i2 = i1; v1 = pv1; i1 = pi1;
            } else if (pv1 > v2 || (pv1 == v2 && pi1 < i2)) { v2 = pv1; i2 = pi1; }
            if (pv2 > v2 || (pv2 == v2 && pi2 < i2)) { v2 = pv2; i2 = pi2; }
        }
        if (v1 - v2 < TAU) {
            const float* xr = x + (size_t)t * DIM;
            float e[2];
            int cand[2] = {i1, i2};
#pragma unroll
            for (int c = 0; c < 2; c++) {
                const float* mr = M + (size_t)(p * 1024 + h * 128 + cand[c]) * 1024;
                float sacc = 0.f;
                for (int d = lane; d < DIM; d += 32)
                    sacc = fmaf(xr[d], mr[d], sacc);
#pragma unroll
                for (int o = 16; o; o >>= 1)
                    sacc += __shfl_xor_sync(0xffffffffu, sacc, o);
                e[c] = sacc;
            }
            if (e[1] > e[0] || (e[1] == e[0] && i2 < i1)) {
                win_v[p] = e[1]; win_i[p] = i2;
            } else { win_v[p] = e[0]; win_i[p] = i1; }
        } else {
            win_v[p] = v1; win_i[p] = i1;
        }
    }
    if (lane == 0) {
        const float sc = win_v[0] + win_v[1];
        gate_out[gw] = sc > 0.f ? sc : 0.f;
        idx_out[gw] = win_i[0] * NKEYS + win_i[1];
    }
}

// ====================== fuse kernels =======================================
__global__ __launch_bounds__(256) void fuse_in_kernel(
    const float* __restrict__ x, const float* __restrict__ in_a,
    const float* __restrict__ in_b, const int* __restrict__ idx,
    const float* __restrict__ gate, float* __restrict__ hidden,
    uint32_t* __restrict__ Hhi, uint32_t* __restrict__ Hlo)
{
    const int t = blockIdx.x;
    const int tid = threadIdx.x;
    __shared__ __align__(16) float xs[DIM];
    __shared__ float red[8][HEADS];
    __shared__ float lin_s[HEADS];

    const float4* xp4 = (const float4*)(x + (size_t)t * DIM);
    ((float4*)xs)[tid] = xp4[tid];

    int id[HEADS]; float gt[HEADS];
#pragma unroll
    for (int h = 0; h < HEADS; h++) {
        id[h] = idx[t * HEADS + h];
        gt[h] = gate[t * HEADS + h];
    }
    __syncthreads();

    const float4 xv = ((const float4*)xs)[tid];
    float part[HEADS];
#pragma unroll
    for (int h = 0; h < HEADS; h++) {
        const float4 av = __ldg((const float4*)&in_a[(size_t)id[h] * DIM] + tid);
        part[h] = xv.x * av.x + xv.y * av.y + xv.z * av.z + xv.w * av.w;
    }
#pragma unroll
    for (int h = 0; h < HEADS; h++)
#pragma unroll
        for (int o = 16; o; o >>= 1)
            part[h] += __shfl_down_sync(0xffffffffu, part[h], o);

    const int wid = tid >> 5, lane = tid & 31;
    if (lane == 0)
#pragma unroll
        for (int h = 0; h < HEADS; h++) red[wid][h] = part[h];
    __syncthreads();
    if (tid < HEADS) {
        float s = 0.f;
#pragma unroll
        for (int w = 0; w < 8; w++) s += red[w][tid];
        lin_s[tid] = s * gt[tid];
    }
    __syncthreads();
    float lin[HEADS];
#pragma unroll
    for (int h = 0; h < HEADS; h++) lin[h] = lin_s[h];

#pragma unroll
    for (int i = 0; i < DINNER / 4 / 256; i++) {
        const int j4 = tid + i * 256;
        float4 v = ((float4*)(hidden + (size_t)t * DINNER))[j4];
#pragma unroll
        for (int h = 0; h < HEADS; h++) {
            const float4 bv = __ldg((const float4*)&in_b[(size_t)id[h] * DINNER] + j4);
            v.x = fmaf(lin[h], bv.x, v.x);
            v.y = fmaf(lin[h], bv.y, v.y);
            v.z = fmaf(lin[h], bv.z, v.z);
            v.w = fmaf(lin[h], bv.w, v.w);
        }
        v.x = 0.5f * v.x * (1.0f + erff(v.x * 0.70710678118654752f));
        v.y = 0.5f * v.y * (1.0f + erff(v.y * 0.70710678118654752f));
        v.z = 0.5f * v.z * (1.0f + erff(v.z * 0.70710678118654752f));
        v.w = 0.5f * v.w * (1.0f + erff(v.w * 0.70710678118654752f));
        ((float4*)(hidden + (size_t)t * DINNER))[j4] = v;

        bf16 h0, h1, h2, h3, l0, l1, l2, l3;
        split_f(v.x, h0, l0); split_f(v.y, h1, l1);
        split_f(v.z, h2, l2); split_f(v.w, h3, l3);
        __nv_bfloat162 H0 = {h0, h1}, H1 = {h2, h3};
        __nv_bfloat162 L0 = {l0, l1}, L1 = {l2, l3};
        const size_t o2 = (size_t)t * (DINNER / 2) + j4 * 2;
        Hhi[o2]     = *(uint32_t*)&H0;
        Hhi[o2 + 1] = *(uint32_t*)&H1;
        Hlo[o2]     = *(uint32_t*)&L0;
        Hlo[o2 + 1] = *(uint32_t*)&L1;
    }
}

__global__ __launch_bounds__(256) void fuse_out_kernel(
    const float* __restrict__ hidden, const float* __restrict__ out_a,
    const float* __restrict__ out_b, const int* __restrict__ idx,
    const float* __restrict__ gate, float* __restrict__ out)
{
    const int t = blockIdx.x;
    const int tid = threadIdx.x;
    __shared__ __align__(16) float hs[DINNER];
    __shared__ float red[8][HEADS];
    __shared__ float lin_s[HEADS];

    const float4* hp4 = (const float4*)(hidden + (size_t)t * DINNER);
    ((float4*)hs)[tid]       = hp4[tid];
    ((float4*)hs)[tid + 256] = hp4[tid + 256];

    int id[HEADS]; float gt[HEADS];
#pragma unroll
    for (int h = 0; h < HEADS; h++) {
        id[h] = idx[t * HEADS + h];
        gt[h] = gate[t * HEADS + h];
    }
    __syncthreads();

    float part[HEADS];
#pragma unroll
    for (int h = 0; h < HEADS; h++) part[h] = 0.f;
#pragma unroll
    for (int i = 0; i < DINNER / 4 / 256; i++) {
        const int d4 = tid + i * 256;
        const float4 hv = ((const float4*)hs)[d4];
#pragma unroll
        for (int h = 0; h < HEADS; h++) {
            const float4 av = __ldg((const float4*)&out_a[(size_t)id[h] * DINNER] + d4);
            part[h] += hv.x * av.x + hv.y * av.y + hv.z * av.z + hv.w * av.w;
        }
    }
#pragma unroll
    for (int h = 0; h < HEADS; h++)
#pragma unroll
        for (int o = 16; o; o >>= 1)
            part[h] += __shfl_down_sync(0xffffffffu, part[h], o);

    const int wid = tid >> 5, lane = tid & 31;
    if (lane == 0)
#pragma unroll
        for (int h = 0; h < HEADS; h++) red[wid][h] = part[h];
    __syncthreads();
    if (tid < HEADS) {
        float s = 0.f;
#pragma unroll
        for (int w = 0; w < 8; w++) s += red[w][tid];
        lin_s[tid] = s * gt[tid];
    }
    __syncthreads();
    float lin[HEADS];
#pragma unroll
    for (int h = 0; h < HEADS; h++) lin[h] = lin_s[h];

    {
        const int j4 = tid;
        float4 v = ((float4*)(out + (size_t)t * DIM))[j4];
#pragma unroll
        for (int h = 0; h < HEADS; h++) {
            const float4 bv = __ldg((const float4*)&out_b[(size_t)id[h] * DIM] + j4);
            v.x = fmaf(lin[h], bv.x, v.x);
            v.y = fmaf(lin[h], bv.y, v.y);
            v.z = fmaf(lin[h], bv.z, v.z);
            v.w = fmaf(lin[h], bv.w, v.w);
        }
        ((float4*)(out + (size_t)t * DIM))[j4] = v;
    }
}

// ===========================================================================
extern "C" void kernel_launch(void* const* d_in, const int* in_sizes, int n_in,
                              void* d_out, int out_size)
{
    const float* x     = (const float*)d_in[0];
    const float* Wq    = (const float*)d_in[1];
    const float* keys  = (const float*)d_in[2];
    const float* W_in  = (const float*)d_in[3];
    const float* W_out = (const float*)d_in[4];
    const float* in_a  = (const float*)d_in[5];
    const float* in_b  = (const float*)d_in[6];
    const float* out_a = (const float*)d_in[7];
    const float* out_b = (const float*)d_in[8];
    float* out = (float*)d_out;

    float *pM, *pSH, *pGate;
    int* pIdx;
    bf16 *pXhi, *pXlo, *pBKWhi, *pBKWlo, *pQhi, *pQlo, *pKhi, *pKlo;
    bf16 *pWOhi, *pWOlo, *pHhi, *pHlo;
    cudaGetSymbolAddress((void**)&pM, g_M);
    cudaGetSymbolAddress((void**)&pSH, g_SH);
    cudaGetSymbolAddress((void**)&pIdx, g_idx);
    cudaGetSymbolAddress((void**)&pGate, g_gate);
    cudaGetSymbolAddress((void**)&pXhi, g_xhi);
    cudaGetSymbolAddress((void**)&pXlo, g_xlo);
    cudaGetSymbolAddress((void**)&pBKWhi, g_BKWhi);
    cudaGetSymbolAddress((void**)&pBKWlo, g_BKWlo);
    cudaGetSymbolAddress((void**)&pQhi, g_Qhi);
    cudaGetSymbolAddress((void**)&pQlo, g_Qlo);
    cudaGetSymbolAddress((void**)&pKhi, g_Khi);
    cudaGetSymbolAddress((void**)&pKlo, g_Klo);
    cudaGetSymbolAddress((void**)&pWOhi, g_WOhi);
    cudaGetSymbolAddress((void**)&pWOlo, g_WOlo);
    cudaGetSymbolAddress((void**)&pHhi, g_Hhi);
    cudaGetSymbolAddress((void**)&pHlo, g_Hlo);

    float* pSim = pSH;
    float* pHid = pSH + (size_t)T_TOK * 2048;
    const size_t BKW_OFF = (size_t)2048 * 1024;

    static bool attr_done = false;
    if (!attr_done) {
        cudaFuncSetAttribute(gemm_b2, cudaFuncAttributeMaxDynamicSharedMemorySize,
                             GEMM_SMEM);
        attr_done = true;
    }

    // --- prepasses: hi/lo splits ---
    split_kernel<<<1024, 256>>>((const float4*)x, (uint32_t*)pXhi,
                                (uint32_t*)pXlo, T_TOK * DIM / 4);
    split_kernel<<<512, 256>>>((const float4*)keys, (uint32_t*)pKhi,
                               (uint32_t*)pKlo, 8 * 128 * 2 * 512 / 4);
    split_kernel<<<512, 256>>>((const float4*)W_in, (uint32_t*)(pBKWhi + BKW_OFF),
                               (uint32_t*)(pBKWlo + BKW_OFF), DINNER * DIM / 4);
    split_kernel<<<512, 256>>>((const float4*)W_out, (uint32_t*)pWOhi,
                               (uint32_t*)pWOlo, DIM * DINNER / 4);
    transpose_split_wq<<<dim3(32, 16, 16), dim3(32, 8)>>>(Wq, pQhi, pQlo);

    // K1: fold keys into Wqt -> M[(p,h,k), d].  z = p*8 + h.
    gemm_b2<<<dim3(1024 / 128, 1, 16), 256, GEMM_SMEM>>>(
        pKhi, pKlo, pQhi, pQlo, pM, 1024, 512, 1024, 512 / 32,
        8, 512, 131072, (size_t)8 * 524288, 524288,
        (size_t)8 * 131072, 131072);
    split_kernel<<<512, 256>>>((const float4*)pM, (uint32_t*)pBKWhi,
                               (uint32_t*)pBKWlo, 2048 * 1024 / 4);

    // K2+K4 merged: [sim | hidden_pre] = x @ [M | W_in]^T  (z batching)
    //   z=0: B = BKW slot 0 (M),    C = sim
    //   z=1: B = BKW slot 1 (W_in), C = hidden_pre
    gemm_b2<<<dim3(2048 / 128, T_TOK / 128, 2), 256, GEMM_SMEM>>>(
        pXhi, pXlo, pBKWhi, pBKWlo, pSH, 1024, 1024, 2048, 1024 / 32,
        1, 0, 0, BKW_OFF, 0, (size_t)T_TOK * 2048, 0);

    // K3: top-1 pair per (t,h) with exact fp32 re-score on ambiguity
    select_kernel<<<(T_TOK * HEADS * 32) / 256, 256>>>(pSim, x, pM, pIdx, pGate);

    // K5: hidden = gelu(hidden_pre + expert-in), emits hi/lo split
    fuse_in_kernel<<<T_TOK, 256>>>(x, in_a, in_b, pIdx, pGate, pHid,
                                   (uint32_t*)pHhi, (uint32_t*)pHlo);

    // K6: out = hidden @ W_out^T  [8192 x 1024], K=2048
    gemm_b2<<<dim3(DIM / 128, T_TOK / 128, 1), 256, GEMM_SMEM>>>(
        pHhi, pHlo, pWOhi, pWOlo, out, DINNER, DINNER, DIM, DINNER / 32,
        1, 0, 0, 0, 0, 0, 0);

    // K7: out += expert-out
    fuse_out_kernel<<<T_TOK, 256>>>(pHid, out_a, out_b, pIdx, pGate, out);
}

// round 17
// speedup vs baseline: 2.2449x; 1.0580x over previous
#include <cuda_runtime.h>
#include <cuda_bf16.h>
#include <math.h>
#include <cstdint>

// ---------------------------------------------------------------------------
// PEER-LoRA fused pipeline, round 13.
// R12 (1216us) + stream-overlap: DRAM-bound gather kernels run concurrently
// with tensor-bound GEMMs via a second stream + event fork/join (graph-
// capturable; streams/events created once on the uncaptured first call).
//   B=4,N=2048 -> T=8192 tokens, DIM=1024, HEADS=8, NUM_KEYS=128,
//   DIM_KEY=512, DIM_INNER=2048, TOPK=1.
// ---------------------------------------------------------------------------

#define T_TOK   8192
#define DIM     1024
#define DINNER  2048
#define HEADS   8
#define NKEYS   128

typedef __nv_bfloat16 bf16;

// fp32 scratch
__device__ __align__(128) float g_M[2048 * 1024];
__device__ __align__(128) float g_sim[T_TOK * 2048];
__device__ __align__(128) float g_hid[T_TOK * DINNER];
__device__ int   g_idx[T_TOK * HEADS];
__device__ float g_gate[T_TOK * HEADS];
__device__ float g_lin_in[T_TOK * HEADS];
__device__ float g_lin_out[T_TOK * HEADS];

// bf16 hi/lo split scratch
__device__ __align__(128) bf16 g_xhi[T_TOK * DIM],      g_xlo[T_TOK * DIM];
__device__ __align__(128) bf16 g_Mhi[2048 * 1024],      g_Mlo[2048 * 1024];
__device__ __align__(128) bf16 g_Qhi[16 * 1024 * 512],  g_Qlo[16 * 1024 * 512];
__device__ __align__(128) bf16 g_Khi[8 * 128 * 2 * 512], g_Klo[8 * 128 * 2 * 512];
__device__ __align__(128) bf16 g_WIhi[DINNER * DIM],    g_WIlo[DINNER * DIM];
__device__ __align__(128) bf16 g_WOhi[DIM * DINNER],    g_WOlo[DIM * DINNER];
__device__ __align__(128) bf16 g_Hhi[T_TOK * DINNER],   g_Hlo[T_TOK * DINNER];

// ============================ helpers ======================================
__device__ __forceinline__ uint32_t smem_u32(const void* p) {
    uint32_t a;
    asm("{ .reg .u64 t; cvta.to.shared.u64 t, %1; cvt.u32.u64 %0, t; }"
        : "=r"(a) : "l"(p));
    return a;
}
__device__ __forceinline__ void cpa16(uint32_t dst, const void* src) {
    asm volatile("cp.async.cg.shared.global [%0], [%1], 16;"
                 :: "r"(dst), "l"(src) : "memory");
}
__device__ __forceinline__ void ldmx4(uint32_t* r, uint32_t addr) {
    asm volatile("ldmatrix.sync.aligned.m8n8.x4.shared.b16 {%0,%1,%2,%3}, [%4];"
                 : "=r"(r[0]), "=r"(r[1]), "=r"(r[2]), "=r"(r[3]) : "r"(addr));
}
__device__ __forceinline__ void mma_bf16(float* d, const uint32_t* a,
                                         uint32_t b0, uint32_t b1) {
    asm volatile(
        "mma.sync.aligned.m16n8k16.row.col.f32.bf16.bf16.f32 "
        "{%0,%1,%2,%3}, {%4,%5,%6,%7}, {%8,%9}, {%0,%1,%2,%3};"
        : "+f"(d[0]), "+f"(d[1]), "+f"(d[2]), "+f"(d[3])
        : "r"(a[0]), "r"(a[1]), "r"(a[2]), "r"(a[3]), "r"(b0), "r"(b1));
}
__device__ __forceinline__ uint32_t swz(int row, int c) {
    return (uint32_t)(((row >> 1) * 128) +
                      ((((((row & 1) << 2) | c)) ^ ((row >> 1) & 7)) << 4));
}
__device__ __forceinline__ void split_f(float v, bf16& h, bf16& l) {
    h = __float2bfloat16(v);
    l = __float2bfloat16(v - __bfloat162float(h));
}

// ======================= split-bf16 GEMM ===================================
#define STAGE_B 32768
#define GSTAGES 3
#define GEMM_SMEM (GSTAGES * STAGE_B)

__global__ __launch_bounds__(256, 2) void gemm_b2(
    const bf16* __restrict__ Ahi, const bf16* __restrict__ Alo,
    const bf16* __restrict__ Bhi, const bf16* __restrict__ Blo,
    float* __restrict__ Cb, int lda, int ldb, int ldc, int nk,
    int zdiv, size_t sah, size_t sal, size_t sbh, size_t sbl,
    size_t sch, size_t scl)
{
    extern __shared__ __align__(1024) char smem[];
    const int z = blockIdx.z;
    const int zh = z / zdiv, zl = z % zdiv;
    const size_t aoff = zh * sah + zl * sal;
    const size_t boff = zh * sbh + zl * sbl;
    float* C = Cb + zh * sch + zl * scl;

    const int tid  = threadIdx.x;
    const int wid  = tid >> 5, lane = tid & 31;
    const int m0   = blockIdx.y * 128;
    const int n0   = blockIdx.x * 128;
    const int m_off = (wid >> 2) * 64;
    const int n_off = (wid & 3) * 32;

    const uint32_t sbase = smem_u32(smem);

    const int q0 = tid * 2;
    const int r0 = q0 >> 2, c0 = q0 & 3;
    const int r1 = (q0 + 1) >> 2, c1 = (q0 + 1) & 3;
    const uint32_t so0 = swz(r0, c0), so1 = swz(r1, c1);
    const bf16* gah  = Ahi + aoff + (size_t)(m0 + r0) * lda + c0 * 8;
    const bf16* gal  = Alo + aoff + (size_t)(m0 + r0) * lda + c0 * 8;
    const bf16* gbh  = Bhi + boff + (size_t)(n0 + r0) * ldb + c0 * 8;
    const bf16* gbl  = Blo + boff + (size_t)(n0 + r0) * ldb + c0 * 8;
    const bf16* gah1 = Ahi + aoff + (size_t)(m0 + r1) * lda + c1 * 8;
    const bf16* gal1 = Alo + aoff + (size_t)(m0 + r1) * lda + c1 * 8;
    const bf16* gbh1 = Bhi + boff + (size_t)(n0 + r1) * ldb + c1 * 8;
    const bf16* gbl1 = Blo + boff + (size_t)(n0 + r1) * ldb + c1 * 8;

    auto load_tile = [&](int kt) {
        const uint32_t b = sbase + (kt % GSTAGES) * STAGE_B;
        const int ke = kt * 32;
        cpa16(b + so0,         gah  + ke);
        cpa16(b + so1,         gah1 + ke);
        cpa16(b + 8192  + so0, gal  + ke);
        cpa16(b + 8192  + so1, gal1 + ke);
        cpa16(b + 16384 + so0, gbh  + ke);
        cpa16(b + 16384 + so1, gbh1 + ke);
        cpa16(b + 24576 + so0, gbl  + ke);
        cpa16(b + 24576 + so1, gbl1 + ke);
        asm volatile("cp.async.commit_group;" ::: "memory");
    };

    const int laneAr = lane & 15;
    const int laneAc = lane >> 4;
    const uint32_t addrA = swz(m_off + laneAr, laneAc);
    const int laneBr = ((lane >> 4) << 3) + (lane & 7);
    const int laneBc = (lane >> 3) & 1;
    const uint32_t addrB = swz(n_off + laneBr, laneBc);

    float acc[4][4][4];
#pragma unroll
    for (int i = 0; i < 4; i++)
#pragma unroll
        for (int j = 0; j < 4; j++)
#pragma unroll
            for (int r = 0; r < 4; r++) acc[i][j][r] = 0.f;

    load_tile(0);
    if (nk > 1) load_tile(1);

    for (int kt = 0; kt < nk; kt++) {
        if (kt + 2 < nk) {
            load_tile(kt + 2);
            asm volatile("cp.async.wait_group 2;" ::: "memory");
        } else if (kt + 1 < nk) {
            asm volatile("cp.async.wait_group 1;" ::: "memory");
        } else {
            asm volatile("cp.async.wait_group 0;" ::: "memory");
        }
        __syncthreads();

        const uint32_t sb = sbase + (kt % GSTAGES) * STAGE_B;
#pragma unroll
        for (int kh = 0; kh < 2; kh++) {
            const uint32_t kx = kh << 5;
            uint32_t bh[2][4], bl[2][4];
#pragma unroll
            for (int np = 0; np < 2; np++) {
                ldmx4(bh[np], (sb + 16384 + addrB + np * 1024) ^ kx);
                ldmx4(bl[np], (sb + 24576 + addrB + np * 1024) ^ kx);
            }
#pragma unroll
            for (int mt = 0; mt < 4; mt++) {
                uint32_t ah[4], al[4];
                ldmx4(ah, (sb + addrA + mt * 1024) ^ kx);
                ldmx4(al, (sb + 8192 + addrA + mt * 1024) ^ kx);
#pragma unroll
                for (int nt = 0; nt < 4; nt++) {
                    const int np = nt >> 1, e = (nt & 1) * 2;
                    mma_bf16(acc[mt][nt], ah, bh[np][e], bh[np][e + 1]);
                    mma_bf16(acc[mt][nt], ah, bl[np][e], bl[np][e + 1]);
                    mma_bf16(acc[mt][nt], al, bh[np][e], bh[np][e + 1]);
                }
            }
        }
        __syncthreads();
    }

    const int lg = lane >> 2, lt = lane & 3;
#pragma unroll
    for (int mt = 0; mt < 4; mt++) {
        const int r = m0 + m_off + mt * 16 + lg;
#pragma unroll
        for (int nt = 0; nt < 4; nt++) {
            const int cc = n0 + n_off + nt * 8 + lt * 2;
            float2 v0 = {acc[mt][nt][0], acc[mt][nt][1]};
            float2 v1 = {acc[mt][nt][2], acc[mt][nt][3]};
            *(float2*)(C + (size_t)r * ldc + cc)       = v0;
            *(float2*)(C + (size_t)(r + 8) * ldc + cc) = v1;
        }
    }
}

// ===================== elementwise hi/lo split =============================
__global__ __launch_bounds__(256) void split_kernel(
    const float4* __restrict__ src, uint32_t* __restrict__ hi,
    uint32_t* __restrict__ lo, int n4)
{
    for (int i = blockIdx.x * blockDim.x + threadIdx.x; i < n4;
         i += gridDim.x * blockDim.x) {
        float4 v = src[i];
        bf16 h0, h1, h2, h3, l0, l1, l2, l3;
        split_f(v.x, h0, l0); split_f(v.y, h1, l1);
        split_f(v.z, h2, l2); split_f(v.w, h3, l3);
        __nv_bfloat162 H0 = {h0, h1}, H1 = {h2, h3};
        __nv_bfloat162 L0 = {l0, l1}, L1 = {l2, l3};
        hi[i * 2]     = *(uint32_t*)&H0;
        hi[i * 2 + 1] = *(uint32_t*)&H1;
        lo[i * 2]     = *(uint32_t*)&L0;
        lo[i * 2 + 1] = *(uint32_t*)&L1;
    }
}

// ============== Wq transpose + split ======================================
__global__ __launch_bounds__(256) void transpose_split_wq(
    const float* __restrict__ Wq, bf16* __restrict__ Qhi, bf16* __restrict__ Qlo)
{
    __shared__ float t[32][33];
    const int z = blockIdx.z;
    const int d0 = blockIdx.x * 32, dk0 = blockIdx.y * 32;
    const int tx = threadIdx.x, ty = threadIdx.y;
#pragma unroll
    for (int i = ty; i < 32; i += 8)
        t[i][tx] = Wq[(size_t)(z * 512 + dk0 + i) * 1024 + d0 + tx];
    __syncthreads();
#pragma unroll
    for (int i = ty; i < 32; i += 8) {
        float v = t[tx][i];
        bf16 h, l;
        split_f(v, h, l);
        size_t o = (size_t)z * 524288 + (size_t)(d0 + i) * 512 + dk0 + tx;
        Qhi[o] = h;
        Qlo[o] = l;
    }
}

// ========================== select =========================================
#define TAU 2e-4f
__global__ __launch_bounds__(256) void select_kernel(
    const float* __restrict__ sim, const float* __restrict__ x,
    const float* __restrict__ M, int* __restrict__ idx_out,
    float* __restrict__ gate_out)
{
    const int gw = (blockIdx.x * blockDim.x + threadIdx.x) >> 5;
    const int lane = threadIdx.x & 31;
    if (gw >= T_TOK * HEADS) return;
    const int t = gw >> 3;
    const int h = gw & 7;

    float win_v[2]; int win_i[2];
#pragma unroll
    for (int p = 0; p < 2; p++) {
        const float* s = sim + (size_t)t * 2048 + p * 1024 + h * 128;
        float v1 = -1e30f, v2 = -1e30f;
        int i1 = 0, i2 = 0;
#pragma unroll
        for (int u = 0; u < 4; u++) {
            const int k = lane + u * 32;
            const float v = s[k];
            if (v > v1 || (v == v1 && k < i1)) { v2 = v1; i2 = i1; v1 = v; i1 = k; }
            else if (v > v2 || (v == v2 && k < i2)) { v2 = v; i2 = k; }
        }
#pragma unroll
        for (int o = 16; o; o >>= 1) {
            float pv1 = __shfl_xor_sync(0xffffffffu, v1, o);
            int   pi1 = __shfl_xor_sync(0xffffffffu, i1, o);
            float pv2 = __shfl_xor_sync(0xffffffffu, v2, o);
            int   pi2 = __shfl_xor_sync(0xffffffffu, i2, o);
            if (pv1 > v1 || (pv1 == v1 && pi1 < i1)) {
                v2 = v1; i2 = i1; v1 = pv1; i1 = pi1;
            } else if (pv1 > v2 || (pv1 == v2 && pi1 < i2)) { v2 = pv1; i2 = pi1; }
            if (pv2 > v2 || (pv2 == v2 && pi2 < i2)) { v2 = pv2; i2 = pi2; }
        }
        if (v1 - v2 < TAU) {
            const float* xr = x + (size_t)t * DIM;
            float e[2];
            int cand[2] = {i1, i2};
#pragma unroll
            for (int c = 0; c < 2; c++) {
                const float* mr = M + (size_t)(p * 1024 + h * 128 + cand[c]) * 1024;
                float sacc = 0.f;
                for (int d = lane; d < DIM; d += 32)
                    sacc = fmaf(xr[d], mr[d], sacc);
#pragma unroll
                for (int o = 16; o; o >>= 1)
                    sacc += __shfl_xor_sync(0xffffffffu, sacc, o);
                e[c] = sacc;
            }
            if (e[1] > e[0] || (e[1] == e[0] && i2 < i1)) {
                win_v[p] = e[1]; win_i[p] = i2;
            } else { win_v[p] = e[0]; win_i[p] = i1; }
        } else {
            win_v[p] = v1; win_i[p] = i1;
        }
    }
    if (lane == 0) {
        const float sc = win_v[0] + win_v[1];
        gate_out[gw] = sc > 0.f ? sc : 0.f;
        idx_out[gw] = win_i[0] * NKEYS + win_i[1];
    }
}

// ================ lin = gate * dot(vec_row, A[idx]) ========================
// one block (256 thr) per token; D = 1024 or 2048 (multiple of 1024)
__global__ __launch_bounds__(256) void lin_kernel(
    const float* __restrict__ vec, const float* __restrict__ A,
    const int* __restrict__ idx, const float* __restrict__ gate,
    float* __restrict__ lin, int D)
{
    const int t = blockIdx.x;
    const int tid = threadIdx.x;
    __shared__ __align__(16) float vs[DINNER];
    __shared__ float red[8][HEADS];

    const float4* vp4 = (const float4*)(vec + (size_t)t * D);
    for (int i = tid; i < D / 4; i += 256) ((float4*)vs)[i] = vp4[i];

    int id[HEADS];
#pragma unroll
    for (int h = 0; h < HEADS; h++) id[h] = idx[t * HEADS + h];
    __syncthreads();

    float part[HEADS];
#pragma unroll
    for (int h = 0; h < HEADS; h++) part[h] = 0.f;
    for (int i = tid; i < D / 4; i += 256) {
        const float4 v = ((const float4*)vs)[i];
#pragma unroll
        for (int h = 0; h < HEADS; h++) {
            const float4 av = __ldg((const float4*)&A[(size_t)id[h] * D] + i);
            part[h] += v.x * av.x + v.y * av.y + v.z * av.z + v.w * av.w;
        }
    }
#pragma unroll
    for (int h = 0; h < HEADS; h++)
#pragma unroll
        for (int o = 16; o; o >>= 1)
            part[h] += __shfl_down_sync(0xffffffffu, part[h], o);

    const int wid = tid >> 5, lane = tid & 31;
    if (lane == 0)
#pragma unroll
        for (int h = 0; h < HEADS; h++) red[wid][h] = part[h];
    __syncthreads();
    if (tid < HEADS) {
        float s = 0.f;
#pragma unroll
        for (int w = 0; w < 8; w++) s += red[w][tid];
        lin[t * HEADS + tid] = s * gate[t * HEADS + tid];
    }
}

// ======= fuse_in_b: hidden = gelu(hidden_pre + Σ lin·in_b), emit split =====
__global__ __launch_bounds__(256) void fuse_in_b_kernel(
    const float* __restrict__ in_b, const int* __restrict__ idx,
    const float* __restrict__ lin_in, float* __restrict__ hidden,
    uint32_t* __restrict__ Hhi, uint32_t* __restrict__ Hlo)
{
    const int t = blockIdx.x;
    const int tid = threadIdx.x;

    int id[HEADS]; float lin[HEADS];
#pragma unroll
    for (int h = 0; h < HEADS; h++) {
        id[h] = idx[t * HEADS + h];
        lin[h] = lin_in[t * HEADS + h];
    }

#pragma unroll
    for (int i = 0; i < DINNER / 4 / 256; i++) {
        const int j4 = tid + i * 256;
        float4 v = ((float4*)(hidden + (size_t)t * DINNER))[j4];
#pragma unroll
        for (int h = 0; h < HEADS; h++) {
            const float4 bv = __ldg((const float4*)&in_b[(size_t)id[h] * DINNER] + j4);
            v.x = fmaf(lin[h], bv.x, v.x);
            v.y = fmaf(lin[h], bv.y, v.y);
            v.z = fmaf(lin[h], bv.z, v.z);
            v.w = fmaf(lin[h], bv.w, v.w);
        }
        v.x = 0.5f * v.x * (1.0f + erff(v.x * 0.70710678118654752f));
        v.y = 0.5f * v.y * (1.0f + erff(v.y * 0.70710678118654752f));
        v.z = 0.5f * v.z * (1.0f + erff(v.z * 0.70710678118654752f));
        v.w = 0.5f * v.w * (1.0f + erff(v.w * 0.70710678118654752f));
        ((float4*)(hidden + (size_t)t * DINNER))[j4] = v;

        bf16 h0, h1, h2, h3, l0, l1, l2, l3;
        split_f(v.x, h0, l0); split_f(v.y, h1, l1);
        split_f(v.z, h2, l2); split_f(v.w, h3, l3);
        __nv_bfloat162 H0 = {h0, h1}, H1 = {h2, h3};
        __nv_bfloat162 L0 = {l0, l1}, L1 = {l2, l3};
        const size_t o2 = (size_t)t * (DINNER / 2) + j4 * 2;
        Hhi[o2]     = *(uint32_t*)&H0;
        Hhi[o2 + 1] = *(uint32_t*)&H1;
        Hlo[o2]     = *(uint32_t*)&L0;
        Hlo[o2 + 1] = *(uint32_t*)&L1;
    }
}

// ============= apply_b: out += Σ lin·B[idx]  (D = DIM) =====================
__global__ __launch_bounds__(256) void apply_b_kernel(
    const float* __restrict__ Bm, const int* __restrict__ idx,
    const float* __restrict__ lin_v, float* __restrict__ out)
{
    const int t = blockIdx.x;
    const int tid = threadIdx.x;

    int id[HEADS]; float lin[HEADS];
#pragma unroll
    for (int h = 0; h < HEADS; h++) {
        id[h] = idx[t * HEADS + h];
        lin[h] = lin_v[t * HEADS + h];
    }

    float4 v = ((float4*)(out + (size_t)t * DIM))[tid];
#pragma unroll
    for (int h = 0; h < HEADS; h++) {
        const float4 bv = __ldg((const float4*)&Bm[(size_t)id[h] * DIM] + tid);
        v.x = fmaf(lin[h], bv.x, v.x);
        v.y = fmaf(lin[h], bv.y, v.y);
        v.z = fmaf(lin[h], bv.z, v.z);
        v.w = fmaf(lin[h], bv.w, v.w);
    }
    ((float4*)(out + (size_t)t * DIM))[tid] = v;
}

// ===========================================================================
extern "C" void kernel_launch(void* const* d_in, const int* in_sizes, int n_in,
                              void* d_out, int out_size)
{
    const float* x     = (const float*)d_in[0];
    const float* Wq    = (const float*)d_in[1];
    const float* keys  = (const float*)d_in[2];
    const float* W_in  = (const float*)d_in[3];
    const float* W_out = (const float*)d_in[4];
    const float* in_a  = (const float*)d_in[5];
    const float* in_b  = (const float*)d_in[6];
    const float* out_a = (const float*)d_in[7];
    const float* out_b = (const float*)d_in[8];
    float* out = (float*)d_out;

    float *pM, *pSim, *pHid, *pGate, *pLinI, *pLinO;
    int* pIdx;
    bf16 *pXhi, *pXlo, *pMhi, *pMlo, *pQhi, *pQlo, *pKhi, *pKlo;
    bf16 *pWIhi, *pWIlo, *pWOhi, *pWOlo, *pHhi, *pHlo;
    cudaGetSymbolAddress((void**)&pM, g_M);
    cudaGetSymbolAddress((void**)&pSim, g_sim);
    cudaGetSymbolAddress((void**)&pHid, g_hid);
    cudaGetSymbolAddress((void**)&pIdx, g_idx);
    cudaGetSymbolAddress((void**)&pGate, g_gate);
    cudaGetSymbolAddress((void**)&pLinI, g_lin_in);
    cudaGetSymbolAddress((void**)&pLinO, g_lin_out);
    cudaGetSymbolAddress((void**)&pXhi, g_xhi);
    cudaGetSymbolAddress((void**)&pXlo, g_xlo);
    cudaGetSymbolAddress((void**)&pMhi, g_Mhi);
    cudaGetSymbolAddress((void**)&pMlo, g_Mlo);
    cudaGetSymbolAddress((void**)&pQhi, g_Qhi);
    cudaGetSymbolAddress((void**)&pQlo, g_Qlo);
    cudaGetSymbolAddress((void**)&pKhi, g_Khi);
    cudaGetSymbolAddress((void**)&pKlo, g_Klo);
    cudaGetSymbolAddress((void**)&pWIhi, g_WIhi);
    cudaGetSymbolAddress((void**)&pWIlo, g_WIlo);
    cudaGetSymbolAddress((void**)&pWOhi, g_WOhi);
    cudaGetSymbolAddress((void**)&pWOlo, g_WOlo);
    cudaGetSymbolAddress((void**)&pHhi, g_Hhi);
    cudaGetSymbolAddress((void**)&pHlo, g_Hlo);

    static cudaStream_t s1 = nullptr;
    static cudaEvent_t eF1, eJ1, eF2, eJ2;
    if (!s1) {
        cudaFuncSetAttribute(gemm_b2, cudaFuncAttributeMaxDynamicSharedMemorySize,
                             GEMM_SMEM);
        cudaStreamCreateWithFlags(&s1, cudaStreamNonBlocking);
        cudaEventCreateWithFlags(&eF1, cudaEventDisableTiming);
        cudaEventCreateWithFlags(&eJ1, cudaEventDisableTiming);
        cudaEventCreateWithFlags(&eF2, cudaEventDisableTiming);
        cudaEventCreateWithFlags(&eJ2, cudaEventDisableTiming);
    }

    // --- prepasses (stream 0) ---
    split_kernel<<<1024, 256>>>((const float4*)x, (uint32_t*)pXhi,
                                (uint32_t*)pXlo, T_TOK * DIM / 4);
    split_kernel<<<512, 256>>>((const float4*)keys, (uint32_t*)pKhi,
                               (uint32_t*)pKlo, 8 * 128 * 2 * 512 / 4);
    split_kernel<<<512, 256>>>((const float4*)W_in, (uint32_t*)pWIhi,
                               (uint32_t*)pWIlo, DINNER * DIM / 4);
    split_kernel<<<512, 256>>>((const float4*)W_out, (uint32_t*)pWOhi,
                               (uint32_t*)pWOlo, DIM * DINNER / 4);
    transpose_split_wq<<<dim3(32, 16, 16), dim3(32, 8)>>>(Wq, pQhi, pQlo);

    // K1: fold -> M; split M
    gemm_b2<<<dim3(1024 / 128, 1, 16), 256, GEMM_SMEM>>>(
        pKhi, pKlo, pQhi, pQlo, pM, 1024, 512, 1024, 512 / 32,
        8, 512, 131072, (size_t)8 * 524288, 524288,
        (size_t)8 * 131072, 131072);
    split_kernel<<<512, 256>>>((const float4*)pM, (uint32_t*)pMhi,
                               (uint32_t*)pMlo, 2048 * 1024 / 4);

    // K2: sim = x @ M^T  (stream 0)
    gemm_b2<<<dim3(2048 / 128, T_TOK / 128, 1), 256, GEMM_SMEM>>>(
        pXhi, pXlo, pMhi, pMlo, pSim, 1024, 1024, 2048, 1024 / 32,
        1, 0, 0, 0, 0, 0, 0);

    // ---- fork 1: hidden_pre GEMM on s1, select+lin_in on stream 0 ----
    cudaEventRecord(eF1, 0);
    cudaStreamWaitEvent(s1, eF1, 0);
    gemm_b2<<<dim3(DINNER / 128, T_TOK / 128, 1), 256, GEMM_SMEM, s1>>>(
        pXhi, pXlo, pWIhi, pWIlo, pHid, 1024, 1024, DINNER, 1024 / 32,
        1, 0, 0, 0, 0, 0, 0);
    cudaEventRecord(eJ1, s1);

    select_kernel<<<(T_TOK * HEADS * 32) / 256, 256>>>(pSim, x, pM, pIdx, pGate);
    lin_kernel<<<T_TOK, 256>>>(x, in_a, pIdx, pGate, pLinI, DIM);

    cudaStreamWaitEvent(0, eJ1, 0);

    // fuse_in_b: hidden = gelu(hidden_pre + Σ lin·in_b), emit hi/lo split
    fuse_in_b_kernel<<<T_TOK, 256>>>(in_b, pIdx, pLinI, pHid,
                                     (uint32_t*)pHhi, (uint32_t*)pHlo);

    // ---- fork 2: out GEMM on s1, lin_out on stream 0 ----
    cudaEventRecord(eF2, 0);
    cudaStreamWaitEvent(s1, eF2, 0);
    gemm_b2<<<dim3(DIM / 128, T_TOK / 128, 1), 256, GEMM_SMEM, s1>>>(
        pHhi, pHlo, pWOhi, pWOlo, out, DINNER, DINNER, DIM, DINNER / 32,
        1, 0, 0, 0, 0, 0, 0);
    cudaEventRecord(eJ2, s1);

    lin_kernel<<<T_TOK, 256>>>(pHid, out_a, pIdx, pGate, pLinO, DINNER);

    cudaStreamWaitEvent(0, eJ2, 0);

    // final: out += Σ lin_out·out_b
    apply_b_kernel<<<T_TOK, 256>>>(out_b, pIdx, pLinO, out);
}